// round 11
// baseline (speedup 1.0000x reference)
#include <cuda_runtime.h>
#include <cuda_bf16.h>
#include <cstdint>

// ---------------------------------------------------------------------------
// Sizes (fixed by the problem)
// ---------------------------------------------------------------------------
#define BATCH    256
#define NAGENTS  8192
#define NEDGES   262144
#define ACT      21

#define L2E 1.4426950408889634f
#define LN2 0.6931471805599453f

// ---------------------------------------------------------------------------
// Scratch (device globals: no allocation allowed)
// ---------------------------------------------------------------------------
__device__ __align__(16) float g_h2[BATCH * 1024];    // conv2 out, row-major
__device__ __align__(16) float g_h2t[1024 * BATCH];   // conv2 out, TRANSPOSED [k][m]
__device__ __align__(16) float g_wt[1024 * 512];      // fc_w transposed [k][n]
__device__ __align__(16) float g_part[4 * BATCH * 512]; // split-K partials
__device__ __align__(16) float g_hidden[BATCH * 512]; // fc out
__device__ float  g_enc[NAGENTS];             // actor_encoding[0]
__device__ float  g_deg[NAGENTS];
__device__ float  g_dinv[NAGENTS];
__device__ __align__(16) float2 g_AB[NAGENTS];  // rank-2 gcn1 aggregates
__device__ __align__(16) float  g_g1[NAGENTS * 16];
__device__ __align__(16) float  g_s[NAGENTS * 16]; // gcn2 input aggregates
__device__ float  g_w2sum[16];
__device__ float  g_b2mean;

// ---------------------------------------------------------------------------
// helpers
// ---------------------------------------------------------------------------
__device__ __forceinline__ unsigned long long fma2(unsigned long long a,
                                                   unsigned long long b,
                                                   unsigned long long c) {
    unsigned long long d;
    asm("fma.rn.f32x2 %0, %1, %2, %3;" : "=l"(d) : "l"(a), "l"(b), "l"(c));
    return d;
}
__device__ __forceinline__ unsigned long long dup2(float v) {
    unsigned u = __float_as_uint(v);
    return ((unsigned long long)u << 32) | (unsigned long long)u;
}
__device__ __forceinline__ unsigned long long pack2(float lo, float hi) {
    return ((unsigned long long)__float_as_uint(hi) << 32) |
           (unsigned long long)__float_as_uint(lo);
}
__device__ __forceinline__ float flo(unsigned long long v) {
    return __uint_as_float((unsigned)v);
}
__device__ __forceinline__ float fhi(unsigned long long v) {
    return __uint_as_float((unsigned)(v >> 32));
}
__device__ __forceinline__ float ex2(float v) {
    float r;
    asm("ex2.approx.ftz.f32 %0, %1;" : "=f"(r) : "f"(v));
    return r;
}
__device__ __forceinline__ void red4(float* p, float a, float b, float c,
                                     float d) {
    asm volatile("red.global.add.v4.f32 [%0], {%1, %2, %3, %4};"
                 :: "l"(p), "f"(a), "f"(b), "f"(c), "f"(d) : "memory");
}
__device__ __forceinline__ void red2(float* p, float a, float b) {
    asm volatile("red.global.add.v2.f32 [%0], {%1, %2};"
                 :: "l"(p), "f"(a), "f"(b) : "memory");
}

// ---------------------------------------------------------------------------
// Fused conv1+conv2 per batch element. One CTA per batch, 8 KB SMEM.
// conv2 weights streamed per-thread from L1 (each thread owns one oc; its 288
// weights are contiguous and quad-broadcast; 72KB total is L1-resident).
// Output h2 written ROW-MAJOR, fully coalesced (f == tid*4+q).
// ---------------------------------------------------------------------------
__global__ void __launch_bounds__(256) k_convs(const float* __restrict__ x,
                                               const float* __restrict__ c1w,
                                               const float* __restrict__ c1b,
                                               const float* __restrict__ c2w,
                                               const float* __restrict__ c2b) {
    __shared__ float xs[848];
    __shared__ float h1s[1152];
    const int b = blockIdx.x, tid = threadIdx.x;

    for (int i = tid; i < 845; i += 256) xs[i] = x[b * 845 + i];
    __syncthreads();

    // conv1: 1152 outputs, 4-5 per thread
    for (int idx = tid; idx < 1152; idx += 256) {
        int oc = idx / 36, p = idx % 36;
        int oy = p / 6, ox = p % 6;
        const float* wb = c1w + oc * 45;
        float acc = c1b[oc];
#pragma unroll
        for (int ic = 0; ic < 5; ic++)
#pragma unroll
            for (int ky = 0; ky < 3; ky++)
#pragma unroll
                for (int kx = 0; kx < 3; kx++)
                    acc += xs[ic * 169 + (2 * oy + ky) * 13 + 2 * ox + kx] *
                           wb[ic * 9 + ky * 3 + kx];
        h1s[idx] = fmaxf(acc, 0.0f);
    }
    __syncthreads();

    // conv2: thread -> (oc = tid/4, oy = tid%4), 4 outputs along ox
    const int oc = tid >> 2, oy = tid & 3;
    const float* wb = c2w + oc * 288;
    float bias = c2b[oc];
    float acc[4];
#pragma unroll
    for (int q = 0; q < 4; q++) acc[q] = bias;

#pragma unroll 4
    for (int ic = 0; ic < 32; ic++) {
#pragma unroll
        for (int ky = 0; ky < 3; ky++) {
            const float* row = &h1s[ic * 36 + (oy + ky) * 6];
            float r0 = row[0], r1 = row[1], r2 = row[2];
            float r3 = row[3], r4 = row[4], r5 = row[5];
            const float* wr = wb + ic * 9 + ky * 3;
            float w0 = __ldg(wr), w1 = __ldg(wr + 1), w2 = __ldg(wr + 2);
            acc[0] += r0 * w0 + r1 * w1 + r2 * w2;
            acc[1] += r1 * w0 + r2 * w1 + r3 * w2;
            acc[2] += r2 * w0 + r3 * w1 + r4 * w2;
            acc[3] += r3 * w0 + r4 * w1 + r5 * w2;
        }
    }
    // f = oc*16 + oy*4 + q = tid*4 + q  ->  one coalesced float4 store
    float4 v = make_float4(fmaxf(acc[0], 0.0f), fmaxf(acc[1], 0.0f),
                           fmaxf(acc[2], 0.0f), fmaxf(acc[3], 0.0f));
    ((float4*)(g_h2 + b * 1024))[tid] = v;
}

// ---------------------------------------------------------------------------
// Transpose g_h2 [256][1024] -> g_h2t [1024][256]. 32x32 tiles.
// ---------------------------------------------------------------------------
__global__ void __launch_bounds__(256) k_h2t() {
    __shared__ float t[32][33];
    const int bm = blockIdx.x & 7;    // 8 m-tiles
    const int bk = blockIdx.x >> 3;   // 32 k-tiles
    const int tx = threadIdx.x & 31, ty = threadIdx.x >> 5;  // 32 x 8
#pragma unroll
    for (int i = 0; i < 32; i += 8)
        t[ty + i][tx] = g_h2[(bm * 32 + ty + i) * 1024 + bk * 32 + tx];
    __syncthreads();
#pragma unroll
    for (int i = 0; i < 32; i += 8)
        g_h2t[(bk * 32 + ty + i) * BATCH + bm * 32 + tx] = t[tx][ty + i];
}

// ---------------------------------------------------------------------------
// Transpose fc_w [512][1024] -> g_wt [1024][512]. 32x32 tiles.
// ---------------------------------------------------------------------------
__global__ void __launch_bounds__(256) k_wt(const float* __restrict__ fc_w) {
    __shared__ float t[32][33];
    const int bk = blockIdx.x & 31;   // 32 k-tiles
    const int bn = blockIdx.x >> 5;   // 16 n-tiles
    const int tx = threadIdx.x & 31, ty = threadIdx.x >> 5;  // 32 x 8
#pragma unroll
    for (int i = 0; i < 32; i += 8)
        t[ty + i][tx] = fc_w[(bn * 32 + ty + i) * 1024 + bk * 32 + tx];
    __syncthreads();
#pragma unroll
    for (int i = 0; i < 32; i += 8)
        g_wt[(bk * 32 + ty + i) * 512 + bn * 32 + tx] = t[tx][ty + i];
}

// ---------------------------------------------------------------------------
// fc GEMM: part[ks] += h2t[kslice]^T x wt[kslice].  C = [256 x 512].
// BM=BN=BK=64, split-K=4 -> 128 CTAs (one wave), 128 threads, 8x4 microtile,
// f32x2 accumulation, all SMEM staging is aligned float4 (no transposes).
// ---------------------------------------------------------------------------
__global__ void __launch_bounds__(128) k_fc_gemm() {
    __shared__ float As[64 * 64];   // [k][m]
    __shared__ float Bs[64 * 64];   // [k][n]
    const int bx = blockIdx.x;
    const int ks = bx >> 5;
    const int mt = (bx >> 3) & 3;
    const int nt = bx & 7;
    const int m0 = mt * 64, n0 = nt * 64;
    const int t  = threadIdx.x;
    const int tc = t & 15, tr = t >> 4;   // tc: 4-col group, tr: 8-row group

    unsigned long long acc[4][4];
#pragma unroll
    for (int p = 0; p < 4; p++)
#pragma unroll
        for (int j = 0; j < 4; j++) acc[p][j] = 0ull;

    const float4* A4g = (const float4*)g_h2t;
    const float4* B4g = (const float4*)g_wt;
    float4* As4w = (float4*)As;
    float4* Bs4w = (float4*)Bs;

    for (int c = 0; c < 4; c++) {
        int k0 = ks * 256 + c * 64;
        __syncthreads();
#pragma unroll
        for (int j = 0; j < 8; j++) {
            int idx = t + 128 * j;           // 0..1023
            int kk = idx >> 4, q = idx & 15;
            As4w[kk * 16 + q] = A4g[((k0 + kk) * BATCH + m0) / 4 + q];
            Bs4w[kk * 16 + q] = B4g[((k0 + kk) * 512 + n0) / 4 + q];
        }
        __syncthreads();

        const float4* As4 = (const float4*)As;
        const float4* Bs4 = (const float4*)Bs;
#pragma unroll 8
        for (int k = 0; k < 64; k++) {
            float4 a0 = As4[k * 16 + tr * 2];
            float4 a1 = As4[k * 16 + tr * 2 + 1];
            float4 bv = Bs4[k * 16 + tc];
            unsigned long long ap[4] = {pack2(a0.x, a0.y), pack2(a0.z, a0.w),
                                        pack2(a1.x, a1.y), pack2(a1.z, a1.w)};
            unsigned long long bd[4] = {dup2(bv.x), dup2(bv.y),
                                        dup2(bv.z), dup2(bv.w)};
#pragma unroll
            for (int p = 0; p < 4; p++)
#pragma unroll
                for (int j = 0; j < 4; j++)
                    acc[p][j] = fma2(ap[p], bd[j], acc[p][j]);
        }
    }

    float* outp = g_part + ks * (BATCH * 512);
#pragma unroll
    for (int p = 0; p < 4; p++) {
        int rlo = m0 + tr * 8 + 2 * p;
        float4 vlo = make_float4(flo(acc[p][0]), flo(acc[p][1]),
                                 flo(acc[p][2]), flo(acc[p][3]));
        float4 vhi = make_float4(fhi(acc[p][0]), fhi(acc[p][1]),
                                 fhi(acc[p][2]), fhi(acc[p][3]));
        *(float4*)(outp + rlo * 512 + n0 + tc * 4) = vlo;
        *(float4*)(outp + (rlo + 1) * 512 + n0 + tc * 4) = vhi;
    }
}

// Epilogue: sum 4 split-K slabs + bias, relu -> g_hidden.
__global__ void __launch_bounds__(256) k_fcsum(const float* __restrict__ fc_b) {
    int gid = blockIdx.x * 256 + threadIdx.x;   // 0..32767 float4s
    const float4* p4 = (const float4*)g_part;
    float4 a = p4[gid];
    float4 b = p4[32768 + gid];
    float4 c = p4[65536 + gid];
    float4 d = p4[98304 + gid];
    float4 bias = ((const float4*)fc_b)[gid & 127];
    float4 r;
    r.x = fmaxf(a.x + b.x + c.x + d.x + bias.x, 0.0f);
    r.y = fmaxf(a.y + b.y + c.y + d.y + bias.y, 0.0f);
    r.z = fmaxf(a.z + b.z + c.z + d.z + bias.z, 0.0f);
    r.w = fmaxf(a.w + b.w + c.w + d.w + bias.w, 0.0f);
    ((float4*)g_hidden)[gid] = r;
}

// ---------------------------------------------------------------------------
// logits + categorical log_prob / entropy; writes action as float.
// Output layout: [action(256) | msg_out(8192) | log_prob(256) | entropy(256)]
// ---------------------------------------------------------------------------
__global__ void __launch_bounds__(256) k_logits(const float* __restrict__ muw,
                                                const float* __restrict__ mub,
                                                const int* __restrict__ action,
                                                float* __restrict__ out) {
    __shared__ float hs[512];
    __shared__ float lg[24];
    const int bb = blockIdx.x, tid = threadIdx.x;
    const int wid = tid >> 5, lane = tid & 31;

    ((float2*)hs)[tid] = ((const float2*)(g_hidden + bb * 512))[tid];
    __syncthreads();

    const float4* h4 = (const float4*)hs;
    for (int a = wid; a < ACT; a += 8) {
        const float4* wr = (const float4*)(muw + a * 512);
        float acc = 0.0f;
#pragma unroll
        for (int i = 0; i < 4; i++) {
            float4 w = wr[lane + i * 32];
            float4 h = h4[lane + i * 32];
            acc += w.x * h.x + w.y * h.y + w.z * h.z + w.w * h.w;
        }
#pragma unroll
        for (int o = 16; o; o >>= 1) acc += __shfl_xor_sync(0xffffffffu, acc, o);
        if (lane == 0) lg[a] = acc + mub[a];
    }
    __syncthreads();

    if (wid == 0) {
        float l = (lane < ACT) ? lg[lane] : -3.4e38f;
        float m = l;
#pragma unroll
        for (int o = 16; o; o >>= 1)
            m = fmaxf(m, __shfl_xor_sync(0xffffffffu, m, o));
        float e  = (lane < ACT) ? __expf(l - m) : 0.0f;
        float el = (lane < ACT) ? e * l : 0.0f;
        float se = e, sel = el;
#pragma unroll
        for (int o = 16; o; o >>= 1) {
            se  += __shfl_xor_sync(0xffffffffu, se, o);
            sel += __shfl_xor_sync(0xffffffffu, sel, o);
        }
        int a = action[bb];
        float la = __shfl_sync(0xffffffffu, l, a);
        if (lane == 0) {
            float lse = m + __logf(se);
            out[BATCH + NAGENTS + bb]     = la - lse;        // log_prob
            out[2 * BATCH + NAGENTS + bb] = lse - sel / se;  // entropy
            out[bb] = (float)a;                              // action
        }
    }
}

// ---------------------------------------------------------------------------
// actor_encoding row 0: enc[j] = hidden[0] . msg_w[j] + msg_b[j]. Warp-dot.
// ---------------------------------------------------------------------------
__global__ void __launch_bounds__(256) k_enc(const float* __restrict__ msg_w,
                                             const float* __restrict__ msg_b) {
    int gtid = blockIdx.x * 256 + threadIdx.x;
    int j    = gtid >> 5;
    int lane = gtid & 31;
    if (j >= NAGENTS) return;
    const float4* w4 = (const float4*)(msg_w + j * 512);
    const float4* h4 = (const float4*)g_hidden;
    float acc = 0.0f;
#pragma unroll
    for (int i = 0; i < 4; i++) {
        float4 w = w4[lane + i * 32];
        float4 h = h4[lane + i * 32];
        acc += w.x * h.x + w.y * h.y + w.z * h.z + w.w * h.w;
    }
#pragma unroll
    for (int o = 16; o; o >>= 1) acc += __shfl_xor_sync(0xffffffffu, acc, o);
    if (lane == 0) g_enc[j] = acc + msg_b[j];
}

// ---------------------------------------------------------------------------
// blocks 0-15: colsum(W2); block 16: mean(b2); blocks 17-48: deg init.
// ---------------------------------------------------------------------------
__global__ void k_w2sum(const float* __restrict__ W2,
                        const float* __restrict__ b2) {
    int tid = threadIdx.x;
    int k   = blockIdx.x;
    if (k >= 17) {
        int i = (k - 17) * 256 + tid;
        if (i < NAGENTS) g_deg[i] = 1.0f;   // self loop
        return;
    }
    __shared__ float red[256];
    const float* src = (k < 16) ? (W2 + k * NAGENTS) : b2;
    float acc = 0.0f;
    for (int j = tid; j < NAGENTS; j += 256) acc += src[j];
    red[tid] = acc;
    __syncthreads();
    for (int s = 128; s; s >>= 1) {
        if (tid < s) red[tid] += red[tid + s];
        __syncthreads();
    }
    if (tid == 0) {
        if (k < 16) g_w2sum[k] = red[0];
        else        g_b2mean  = red[0] * (1.0f / (float)NAGENTS);
    }
}

// ---------------------------------------------------------------------------
// GCN norm + aggregation
// ---------------------------------------------------------------------------
__global__ void k_deg(const int* __restrict__ ei) {
    int e = blockIdx.x * 256 + threadIdx.x;
    if (e < NEDGES) atomicAdd(&g_deg[ei[2 * e + 1]], 1.0f);
}
__global__ void k_dinvAB(const float* __restrict__ xm) {
    int i = blockIdx.x * 256 + threadIdx.x;
    if (i >= NAGENTS) return;
    float dv = rsqrtf(g_deg[i]);
    g_dinv[i] = dv;
    float d2 = dv * dv;                       // self-loop norm
    g_AB[i] = make_float2(d2 * xm[i], d2 * g_enc[i]);
}
__global__ void k_edge1(const int* __restrict__ ei,
                        const float* __restrict__ xm) {
    int e = blockIdx.x * 256 + threadIdx.x;
    if (e >= NEDGES) return;
    int s = ei[2 * e], d = ei[2 * e + 1];
    float nrm = g_dinv[s] * g_dinv[d];
    red2((float*)&g_AB[d], nrm * xm[s], nrm * g_enc[s]);
}
// g1 = relu(AB @ W1 + b1); s initialized with the self-loop term d^2 * g1
__global__ void k_g1s(const float* __restrict__ w1,
                      const float* __restrict__ b1) {
    int idx = blockIdx.x * 256 + threadIdx.x;
    if (idx >= NAGENTS * 16) return;
    int i = idx >> 4, k = idx & 15;
    float2 ab = g_AB[i];
    float v = fmaxf(ab.x * w1[k] + ab.y * w1[16 + k] + b1[k], 0.0f);
    g_g1[idx] = v;
    float dv = g_dinv[i];
    g_s[idx] = dv * dv * v;
}
__global__ void k_edge2(const int* __restrict__ ei) {
    int e = blockIdx.x * 256 + threadIdx.x;
    if (e >= NEDGES) return;
    int s = ei[2 * e], d = ei[2 * e + 1];
    float nrm = g_dinv[s] * g_dinv[d];
    const float4* g1r = (const float4*)(g_g1 + s * 16);
    float* sd = g_s + d * 16;
#pragma unroll
    for (int q = 0; q < 4; q++) {
        float4 v = g1r[q];
        red4(sd + q * 4, nrm * v.x, nrm * v.y, nrm * v.z, nrm * v.w);
    }
}

// ---------------------------------------------------------------------------
// K12: msg_out[i] = mean_j(g_ij) - lse_j(g_ij) with g_ij = s[i].W2[:,j]+b2[j].
// 16 rows/CTA, W2 streamed in 16x1024 SMEM chunks, f32x2 FMA.
// log2-domain accumulation (s, b2 pre-scaled by log2 e) -> raw ex2, no
// max-tracking needed (|g| bounded analytically far below overflow).
// ---------------------------------------------------------------------------
#define MS_CHUNK 1024
#define MS_ROWS  16
#define MS_SMEM  (16 * MS_CHUNK * 4 + MS_ROWS * 16 * 8)

__global__ void __launch_bounds__(256) k_msgout(const float* __restrict__ W2,
                                                const float* __restrict__ b2,
                                                float* __restrict__ out) {
    extern __shared__ char smraw[];
    float* wsm = (float*)smraw;                                    // 16*1024 f
    unsigned long long* sdup =
        (unsigned long long*)(smraw + 16 * MS_CHUNK * 4);          // 256 u64

    const int tid  = threadIdx.x;
    const int row0 = blockIdx.x * MS_ROWS;

    {   // duplicated, log2e-scaled s values for f32x2 broadcast
        int r = tid >> 4, k = tid & 15;
        sdup[tid] = dup2(g_s[(row0 + r) * 16 + k] * L2E);
    }

    float sr[MS_ROWS];
#pragma unroll
    for (int r = 0; r < MS_ROWS; r++) sr[r] = 0.0f;

    const float4* gw4 = (const float4*)W2;

    for (int chunk = 0; chunk < NAGENTS / MS_CHUNK; chunk++) {
        int base = chunk * MS_CHUNK;
        __syncthreads();
#pragma unroll
        for (int k = 0; k < 16; k++)
            ((float4*)wsm)[k * 256 + tid] = gw4[(k * NAGENTS + base) / 4 + tid];
        float4 bb = ((const float4*)(b2 + base))[tid];
        __syncthreads();

        unsigned long long acc0[MS_ROWS], acc1[MS_ROWS];
        unsigned long long b01 = pack2(bb.x * L2E, bb.y * L2E);
        unsigned long long b23 = pack2(bb.z * L2E, bb.w * L2E);
#pragma unroll
        for (int r = 0; r < MS_ROWS; r++) { acc0[r] = b01; acc1[r] = b23; }

        const ulonglong2* wU2 = (const ulonglong2*)wsm;
#pragma unroll
        for (int k = 0; k < 16; k++) {
            ulonglong2 w = wU2[k * 256 + tid];    // LDS.128, conflict-free
#pragma unroll
            for (int r = 0; r < MS_ROWS; r++) {
                unsigned long long sv = sdup[r * 16 + k];  // broadcast
                acc0[r] = fma2(w.x, sv, acc0[r]);
                acc1[r] = fma2(w.y, sv, acc1[r]);
            }
        }
#pragma unroll
        for (int r = 0; r < MS_ROWS; r++) {
            sr[r] += ex2(flo(acc0[r])) + ex2(fhi(acc0[r])) +
                     ex2(flo(acc1[r])) + ex2(fhi(acc1[r]));
        }
    }

    // block sum-reduce per row; alias onto wsm (16KB)
    __syncthreads();
    float* rs = wsm;              // [16][256]
#pragma unroll
    for (int r = 0; r < MS_ROWS; r++) rs[r * 256 + tid] = sr[r];
    for (int step = 128; step > 0; step >>= 1) {
        __syncthreads();
        if (tid < step) {
#pragma unroll
            for (int r = 0; r < MS_ROWS; r++)
                rs[r * 256 + tid] += rs[r * 256 + tid + step];
        }
    }
    __syncthreads();
    if (tid < MS_ROWS) {
        int row = row0 + tid;
        float lse = LN2 * __log2f(rs[tid * 256]);
        float acc = 0.0f;
#pragma unroll
        for (int k = 0; k < 16; k++) acc += g_s[row * 16 + k] * g_w2sum[k];
        out[BATCH + row] = acc * (1.0f / (float)NAGENTS) + g_b2mean - lse;
    }
}

// ---------------------------------------------------------------------------
// launch
// ---------------------------------------------------------------------------
extern "C" void kernel_launch(void* const* d_in, const int* in_sizes, int n_in,
                              void* d_out, int out_size) {
    const float* x    = (const float*)d_in[0];
    const float* xmsg = (const float*)d_in[1];
    const int*   ei   = (const int*)d_in[2];
    const int*   act  = (const int*)d_in[3];
    const float* c1w  = (const float*)d_in[4];
    const float* c1b  = (const float*)d_in[5];
    const float* c2w  = (const float*)d_in[6];
    const float* c2b  = (const float*)d_in[7];
    const float* fcw  = (const float*)d_in[8];
    const float* fcb  = (const float*)d_in[9];
    const float* muw  = (const float*)d_in[10];
    const float* mub  = (const float*)d_in[11];
    const float* msw  = (const float*)d_in[12];
    const float* msb  = (const float*)d_in[13];
    const float* g1w  = (const float*)d_in[14];
    const float* g1b  = (const float*)d_in[15];
    const float* g2w  = (const float*)d_in[16];
    const float* g2b  = (const float*)d_in[17];
    float* out = (float*)d_out;

    cudaFuncSetAttribute(k_msgout, cudaFuncAttributeMaxDynamicSharedMemorySize,
                         MS_SMEM);

    // Independent preprocessing
    k_wt<<<512, 256>>>(fcw);
    k_w2sum<<<49, 256>>>(g2w, g2b);
    k_deg<<<NEDGES / 256, 256>>>(ei);

    // CNN / actor head
    k_convs<<<BATCH, 256>>>(x, c1w, c1b, c2w, c2b);
    k_h2t<<<256, 256>>>();
    k_fc_gemm<<<128, 128>>>();
    k_fcsum<<<128, 256>>>(fcb);
    k_logits<<<BATCH, 256>>>(muw, mub, act, out);
    k_enc<<<NAGENTS / 8, 256>>>(msw, msb);

    // GCN
    k_dinvAB<<<NAGENTS / 256, 256>>>(xmsg);
    k_edge1<<<NEDGES / 256, 256>>>(ei, xmsg);
    k_g1s<<<NAGENTS * 16 / 256, 256>>>(g1w, g1b);
    k_edge2<<<NEDGES / 256, 256>>>(ei);

    // streaming log-softmax-mean over the virtual [N,N] matrix
    k_msgout<<<NAGENTS / MS_ROWS, 256, MS_SMEM>>>(g2w, g2b, out);
}

// round 12
// speedup vs baseline: 1.0865x; 1.0865x over previous
#include <cuda_runtime.h>
#include <cuda_bf16.h>
#include <cstdint>

// ---------------------------------------------------------------------------
// Sizes (fixed by the problem)
// ---------------------------------------------------------------------------
#define BATCH    256
#define NAGENTS  8192
#define NEDGES   262144
#define ACT      21

#define L2E 1.4426950408889634f
#define LN2 0.6931471805599453f

// ---------------------------------------------------------------------------
// Scratch (device globals: no allocation allowed)
// ---------------------------------------------------------------------------
__device__ __align__(16) float g_h2t[1024 * BATCH];   // conv2 out, TRANSPOSED [k][m]
__device__ __align__(16) float g_wt[1024 * 512];      // fc_w transposed [k][n]
__device__ __align__(16) float g_w2tp[288 * 65];      // conv2 w, padded transpose [j][oc]
__device__ __align__(16) float g_part[4 * BATCH * 512]; // split-K partials
__device__ float  g_enc[NAGENTS];             // actor_encoding[0]
__device__ float  g_deg[NAGENTS];
__device__ float  g_dinv[NAGENTS];
__device__ __align__(16) float2 g_AB[NAGENTS];  // rank-2 gcn1 aggregates
__device__ __align__(16) float  g_g1[NAGENTS * 16];
__device__ __align__(16) float  g_s[NAGENTS * 16]; // gcn2 input aggregates
__device__ float  g_w2sum[16];
__device__ float  g_b2mean;

// ---------------------------------------------------------------------------
// helpers
// ---------------------------------------------------------------------------
__device__ __forceinline__ unsigned long long fma2(unsigned long long a,
                                                   unsigned long long b,
                                                   unsigned long long c) {
    unsigned long long d;
    asm("fma.rn.f32x2 %0, %1, %2, %3;" : "=l"(d) : "l"(a), "l"(b), "l"(c));
    return d;
}
__device__ __forceinline__ unsigned long long dup2(float v) {
    unsigned u = __float_as_uint(v);
    return ((unsigned long long)u << 32) | (unsigned long long)u;
}
__device__ __forceinline__ unsigned long long pack2(float lo, float hi) {
    return ((unsigned long long)__float_as_uint(hi) << 32) |
           (unsigned long long)__float_as_uint(lo);
}
__device__ __forceinline__ float flo(unsigned long long v) {
    return __uint_as_float((unsigned)v);
}
__device__ __forceinline__ float fhi(unsigned long long v) {
    return __uint_as_float((unsigned)(v >> 32));
}
__device__ __forceinline__ float ex2(float v) {
    float r;
    asm("ex2.approx.ftz.f32 %0, %1;" : "=f"(r) : "f"(v));
    return r;
}
__device__ __forceinline__ void red4(float* p, float a, float b, float c,
                                     float d) {
    asm volatile("red.global.add.v4.f32 [%0], {%1, %2, %3, %4};"
                 :: "l"(p), "f"(a), "f"(b), "f"(c), "f"(d) : "memory");
}
__device__ __forceinline__ void red2(float* p, float a, float b) {
    asm volatile("red.global.add.v2.f32 [%0], {%1, %2};"
                 :: "l"(p), "f"(a), "f"(b) : "memory");
}

// ---------------------------------------------------------------------------
// k_pre: all independent preprocessing in ONE kernel.
//  blocks [0,512)    : transpose fc_w [512][1024] -> g_wt [1024][512]
//  blocks [512,530)  : pad-transpose c2w [64][288] -> g_w2tp [288][65]
//  blocks [530,547)  : colsum(W2) (16) + mean(b2) (1)
//  blocks [547,579)  : g_deg = 1 (self loops)
// ---------------------------------------------------------------------------
__global__ void __launch_bounds__(256) k_pre(const float* __restrict__ fc_w,
                                             const float* __restrict__ c2w,
                                             const float* __restrict__ W2,
                                             const float* __restrict__ b2) {
    const int bid = blockIdx.x, tid = threadIdx.x;
    if (bid < 512) {
        __shared__ float t[32][33];
        const int bk = bid & 31;   // 32 k-tiles
        const int bn = bid >> 5;   // 16 n-tiles
        const int tx = tid & 31, ty = tid >> 5;  // 32 x 8
#pragma unroll
        for (int i = 0; i < 32; i += 8)
            t[ty + i][tx] = fc_w[(bn * 32 + ty + i) * 1024 + bk * 32 + tx];
        __syncthreads();
#pragma unroll
        for (int i = 0; i < 32; i += 8)
            g_wt[(bk * 32 + ty + i) * 512 + bn * 32 + tx] = t[tx][ty + i];
    } else if (bid < 530) {
        int base = (bid - 512) * 1024;
#pragma unroll
        for (int q = 0; q < 4; q++) {
            int idx = base + q * 256 + tid;
            if (idx < 64 * 288) {
                int oc = idx / 288, j = idx - oc * 288;
                g_w2tp[j * 65 + oc] = c2w[idx];
            }
        }
    } else if (bid < 547) {
        int k = bid - 530;
        __shared__ float red[256];
        const float* src = (k < 16) ? (W2 + k * NAGENTS) : b2;
        float acc = 0.0f;
        for (int j = tid; j < NAGENTS; j += 256) acc += src[j];
        red[tid] = acc;
        __syncthreads();
        for (int s = 128; s; s >>= 1) {
            if (tid < s) red[tid] += red[tid + s];
            __syncthreads();
        }
        if (tid == 0) {
            if (k < 16) g_w2sum[k] = red[0];
            else        g_b2mean  = red[0] * (1.0f / (float)NAGENTS);
        }
    } else {
        int i = (bid - 547) * 256 + tid;
        if (i < NAGENTS) g_deg[i] = 1.0f;
    }
}

// ---------------------------------------------------------------------------
// Fused conv1+conv2 per batch element. One CTA per batch.
// conv2 weights staged via pure coalesced float4 copy from the pre-padded
// g_w2tp ([j][65] layout -> conflict-free quad-broadcast reads).
// Writes h2 TRANSPOSED directly (g_h2t[k][m]) for the GEMM.
// ---------------------------------------------------------------------------
__global__ void __launch_bounds__(256) k_convs(const float* __restrict__ x,
                                               const float* __restrict__ c1w,
                                               const float* __restrict__ c1b,
                                               const float* __restrict__ c2b) {
    __shared__ float xs[848];
    __shared__ float h1s[1152];
    __shared__ __align__(16) float w2s[288 * 65];
    const int b = blockIdx.x, tid = threadIdx.x;

    // stage: pure float4 copies, no div/mod, coalesced
    {
        const float4* src = (const float4*)g_w2tp;
        float4* dst = (float4*)w2s;
        for (int i = tid; i < (288 * 65) / 4; i += 256) dst[i] = src[i];
    }
    for (int i = tid; i < 845; i += 256) xs[i] = x[b * 845 + i];
    __syncthreads();

    // conv1: 1152 outputs, 4-5 per thread
    for (int idx = tid; idx < 1152; idx += 256) {
        int oc = idx / 36, p = idx % 36;
        int oy = p / 6, ox = p % 6;
        const float* wb = c1w + oc * 45;
        float acc = c1b[oc];
#pragma unroll
        for (int ic = 0; ic < 5; ic++)
#pragma unroll
            for (int ky = 0; ky < 3; ky++)
#pragma unroll
                for (int kx = 0; kx < 3; kx++)
                    acc += xs[ic * 169 + (2 * oy + ky) * 13 + 2 * ox + kx] *
                           wb[ic * 9 + ky * 3 + kx];
        h1s[idx] = fmaxf(acc, 0.0f);
    }
    __syncthreads();

    // conv2: thread -> (oc = tid/4, oy = tid%4), 4 outputs along ox
    const int oc = tid >> 2, oy = tid & 3;
    float bias = c2b[oc];
    float acc[4];
#pragma unroll
    for (int q = 0; q < 4; q++) acc[q] = bias;

#pragma unroll 4
    for (int ic = 0; ic < 32; ic++) {
#pragma unroll
        for (int ky = 0; ky < 3; ky++) {
            const float* row = &h1s[ic * 36 + (oy + ky) * 6];
            float r0 = row[0], r1 = row[1], r2 = row[2];
            float r3 = row[3], r4 = row[4], r5 = row[5];
            const float* wr = &w2s[(ic * 9 + ky * 3) * 65 + oc];
            float w0 = wr[0], w1 = wr[65], w2 = wr[130];
            acc[0] += r0 * w0 + r1 * w1 + r2 * w2;
            acc[1] += r1 * w0 + r2 * w1 + r3 * w2;
            acc[2] += r2 * w0 + r3 * w1 + r4 * w2;
            acc[3] += r3 * w0 + r4 * w1 + r5 * w2;
        }
    }
    int f0 = oc * 16 + oy * 4;
#pragma unroll
    for (int q = 0; q < 4; q++)
        g_h2t[(f0 + q) * BATCH + b] = fmaxf(acc[q], 0.0f);
}

// ---------------------------------------------------------------------------
// fc GEMM: part[ks] += h2t[kslice]^T x wt[kslice].  C = [256 x 512].
// BM=BN=BK=64, split-K=4 -> 128 CTAs (one wave), 128 threads, 8x4 microtile,
// f32x2 accumulation, all SMEM staging is aligned float4 (no transposes).
// ---------------------------------------------------------------------------
__global__ void __launch_bounds__(128) k_fc_gemm() {
    __shared__ float As[64 * 64];   // [k][m]
    __shared__ float Bs[64 * 64];   // [k][n]
    const int bx = blockIdx.x;
    const int ks = bx >> 5;
    const int mt = (bx >> 3) & 3;
    const int nt = bx & 7;
    const int m0 = mt * 64, n0 = nt * 64;
    const int t  = threadIdx.x;
    const int tc = t & 15, tr = t >> 4;   // tc: 4-col group, tr: 8-row group

    unsigned long long acc[4][4];
#pragma unroll
    for (int p = 0; p < 4; p++)
#pragma unroll
        for (int j = 0; j < 4; j++) acc[p][j] = 0ull;

    const float4* A4g = (const float4*)g_h2t;
    const float4* B4g = (const float4*)g_wt;
    float4* As4w = (float4*)As;
    float4* Bs4w = (float4*)Bs;

    for (int c = 0; c < 4; c++) {
        int k0 = ks * 256 + c * 64;
        __syncthreads();
#pragma unroll
        for (int j = 0; j < 8; j++) {
            int idx = t + 128 * j;           // 0..1023
            int kk = idx >> 4, q = idx & 15;
            As4w[kk * 16 + q] = A4g[((k0 + kk) * BATCH + m0) / 4 + q];
            Bs4w[kk * 16 + q] = B4g[((k0 + kk) * 512 + n0) / 4 + q];
        }
        __syncthreads();

        const float4* As4 = (const float4*)As;
        const float4* Bs4 = (const float4*)Bs;
#pragma unroll 8
        for (int k = 0; k < 64; k++) {
            float4 a0 = As4[k * 16 + tr * 2];
            float4 a1 = As4[k * 16 + tr * 2 + 1];
            float4 bv = Bs4[k * 16 + tc];
            unsigned long long ap[4] = {pack2(a0.x, a0.y), pack2(a0.z, a0.w),
                                        pack2(a1.x, a1.y), pack2(a1.z, a1.w)};
            unsigned long long bd[4] = {dup2(bv.x), dup2(bv.y),
                                        dup2(bv.z), dup2(bv.w)};
#pragma unroll
            for (int p = 0; p < 4; p++)
#pragma unroll
                for (int j = 0; j < 4; j++)
                    acc[p][j] = fma2(ap[p], bd[j], acc[p][j]);
        }
    }

    float* outp = g_part + ks * (BATCH * 512);
#pragma unroll
    for (int p = 0; p < 4; p++) {
        int rlo = m0 + tr * 8 + 2 * p;
        float4 vlo = make_float4(flo(acc[p][0]), flo(acc[p][1]),
                                 flo(acc[p][2]), flo(acc[p][3]));
        float4 vhi = make_float4(fhi(acc[p][0]), fhi(acc[p][1]),
                                 fhi(acc[p][2]), fhi(acc[p][3]));
        *(float4*)(outp + rlo * 512 + n0 + tc * 4) = vlo;
        *(float4*)(outp + (rlo + 1) * 512 + n0 + tc * 4) = vhi;
    }
}

// ---------------------------------------------------------------------------
// Reconstruct one hidden row from the 4 split-K slabs + bias + relu into smem.
// ---------------------------------------------------------------------------
__device__ __forceinline__ void load_hidden_row(float* hs, int row,
                                                const float* __restrict__ fcb,
                                                int tid) {
    const float2* p0 = (const float2*)(g_part + row * 512);
    const float2* p1 = (const float2*)(g_part + 131072 + row * 512);
    const float2* p2 = (const float2*)(g_part + 262144 + row * 512);
    const float2* p3 = (const float2*)(g_part + 393216 + row * 512);
    float2 a = p0[tid], b = p1[tid], c = p2[tid], d = p3[tid];
    float2 bias = ((const float2*)fcb)[tid];
    ((float2*)hs)[tid] = make_float2(
        fmaxf(a.x + b.x + c.x + d.x + bias.x, 0.0f),
        fmaxf(a.y + b.y + c.y + d.y + bias.y, 0.0f));
}

// ---------------------------------------------------------------------------
// k_lgenc: fused logits head + actor-encoding + gcn node prep.
//  blocks [0,256):   logits/log_prob/entropy/action for batch row bid
//  blocks [256,1280): enc[j] (8 j per block) + dinv[j] + self-loop AB[j]
// Output layout: [action(256) | msg_out(8192) | log_prob(256) | entropy(256)]
// ---------------------------------------------------------------------------
__global__ void __launch_bounds__(256) k_lgenc(const float* __restrict__ fcb,
                                               const float* __restrict__ muw,
                                               const float* __restrict__ mub,
                                               const int* __restrict__ action,
                                               const float* __restrict__ msw,
                                               const float* __restrict__ msb,
                                               const float* __restrict__ xm,
                                               float* __restrict__ out) {
    __shared__ float hs[512];
    __shared__ float lg[24];
    const int bid = blockIdx.x, tid = threadIdx.x;
    const int wid = tid >> 5, lane = tid & 31;

    if (bid < 256) {
        load_hidden_row(hs, bid, fcb, tid);
        __syncthreads();

        const float4* h4 = (const float4*)hs;
        for (int a = wid; a < ACT; a += 8) {
            const float4* wr = (const float4*)(muw + a * 512);
            float acc = 0.0f;
#pragma unroll
            for (int i = 0; i < 4; i++) {
                float4 w = wr[lane + i * 32];
                float4 h = h4[lane + i * 32];
                acc += w.x * h.x + w.y * h.y + w.z * h.z + w.w * h.w;
            }
#pragma unroll
            for (int o = 16; o; o >>= 1)
                acc += __shfl_xor_sync(0xffffffffu, acc, o);
            if (lane == 0) lg[a] = acc + mub[a];
        }
        __syncthreads();

        if (wid == 0) {
            float l = (lane < ACT) ? lg[lane] : -3.4e38f;
            float m = l;
#pragma unroll
            for (int o = 16; o; o >>= 1)
                m = fmaxf(m, __shfl_xor_sync(0xffffffffu, m, o));
            float e  = (lane < ACT) ? __expf(l - m) : 0.0f;
            float el = (lane < ACT) ? e * l : 0.0f;
            float se = e, sel = el;
#pragma unroll
            for (int o = 16; o; o >>= 1) {
                se  += __shfl_xor_sync(0xffffffffu, se, o);
                sel += __shfl_xor_sync(0xffffffffu, sel, o);
            }
            int a = action[bid];
            float la = __shfl_sync(0xffffffffu, l, a);
            if (lane == 0) {
                float lse = m + __logf(se);
                out[BATCH + NAGENTS + bid]     = la - lse;        // log_prob
                out[2 * BATCH + NAGENTS + bid] = lse - sel / se;  // entropy
                out[bid] = (float)a;                              // action
            }
        }
    } else {
        load_hidden_row(hs, 0, fcb, tid);
        __syncthreads();

        const int j = (bid - 256) * 8 + wid;
        const float4* w4 = (const float4*)(msw + j * 512);
        const float4* h4 = (const float4*)hs;
        float acc = 0.0f;
#pragma unroll
        for (int i = 0; i < 4; i++) {
            float4 w = w4[lane + i * 32];
            float4 h = h4[lane + i * 32];
            acc += w.x * h.x + w.y * h.y + w.z * h.z + w.w * h.w;
        }
#pragma unroll
        for (int o = 16; o; o >>= 1) acc += __shfl_xor_sync(0xffffffffu, acc, o);
        if (lane == 0) {
            float e = acc + msb[j];
            g_enc[j] = e;
            float dv = rsqrtf(g_deg[j]);
            g_dinv[j] = dv;
            float d2 = dv * dv;               // self-loop norm
            g_AB[j] = make_float2(d2 * xm[j], d2 * e);
        }
    }
}

// ---------------------------------------------------------------------------
// GCN edge aggregation
// ---------------------------------------------------------------------------
__global__ void k_deg(const int* __restrict__ ei) {
    int e = blockIdx.x * 256 + threadIdx.x;
    if (e < NEDGES) atomicAdd(&g_deg[ei[2 * e + 1]], 1.0f);
}
__global__ void k_edge1(const int* __restrict__ ei,
                        const float* __restrict__ xm) {
    int e = blockIdx.x * 256 + threadIdx.x;
    if (e >= NEDGES) return;
    int s = ei[2 * e], d = ei[2 * e + 1];
    float nrm = g_dinv[s] * g_dinv[d];
    red2((float*)&g_AB[d], nrm * xm[s], nrm * g_enc[s]);
}
// g1 = relu(AB @ W1 + b1); s initialized with the self-loop term d^2 * g1
__global__ void k_g1s(const float* __restrict__ w1,
                      const float* __restrict__ b1) {
    int idx = blockIdx.x * 256 + threadIdx.x;
    if (idx >= NAGENTS * 16) return;
    int i = idx >> 4, k = idx & 15;
    float2 ab = g_AB[i];
    float v = fmaxf(ab.x * w1[k] + ab.y * w1[16 + k] + b1[k], 0.0f);
    g_g1[idx] = v;
    float dv = g_dinv[i];
    g_s[idx] = dv * dv * v;
}
__global__ void k_edge2(const int* __restrict__ ei) {
    int e = blockIdx.x * 256 + threadIdx.x;
    if (e >= NEDGES) return;
    int s = ei[2 * e], d = ei[2 * e + 1];
    float nrm = g_dinv[s] * g_dinv[d];
    const float4* g1r = (const float4*)(g_g1 + s * 16);
    float* sd = g_s + d * 16;
#pragma unroll
    for (int q = 0; q < 4; q++) {
        float4 v = g1r[q];
        red4(sd + q * 4, nrm * v.x, nrm * v.y, nrm * v.z, nrm * v.w);
    }
}

// ---------------------------------------------------------------------------
// K12: msg_out[i] = mean_j(g_ij) - lse_j(g_ij) with g_ij = s[i].W2[:,j]+b2[j].
// 16 rows/CTA, W2 streamed in 16x1024 SMEM chunks, f32x2 FMA.
// log2-domain accumulation (s, b2 pre-scaled by log2 e) -> raw ex2, no
// max-tracking needed (|g| bounded analytically far below overflow).
// ---------------------------------------------------------------------------
#define MS_CHUNK 1024
#define MS_ROWS  16
#define MS_SMEM  (16 * MS_CHUNK * 4 + MS_ROWS * 16 * 8)

__global__ void __launch_bounds__(256) k_msgout(const float* __restrict__ W2,
                                                const float* __restrict__ b2,
                                                float* __restrict__ out) {
    extern __shared__ char smraw[];
    float* wsm = (float*)smraw;                                    // 16*1024 f
    unsigned long long* sdup =
        (unsigned long long*)(smraw + 16 * MS_CHUNK * 4);          // 256 u64

    const int tid  = threadIdx.x;
    const int row0 = blockIdx.x * MS_ROWS;

    {   // duplicated, log2e-scaled s values for f32x2 broadcast
        int r = tid >> 4, k = tid & 15;
        sdup[tid] = dup2(g_s[(row0 + r) * 16 + k] * L2E);
    }

    float sr[MS_ROWS];
#pragma unroll
    for (int r = 0; r < MS_ROWS; r++) sr[r] = 0.0f;

    const float4* gw4 = (const float4*)W2;

    for (int chunk = 0; chunk < NAGENTS / MS_CHUNK; chunk++) {
        int base = chunk * MS_CHUNK;
        __syncthreads();
#pragma unroll
        for (int k = 0; k < 16; k++)
            ((float4*)wsm)[k * 256 + tid] = gw4[(k * NAGENTS + base) / 4 + tid];
        float4 bb = ((const float4*)(b2 + base))[tid];
        __syncthreads();

        unsigned long long acc0[MS_ROWS], acc1[MS_ROWS];
        unsigned long long b01 = pack2(bb.x * L2E, bb.y * L2E);
        unsigned long long b23 = pack2(bb.z * L2E, bb.w * L2E);
#pragma unroll
        for (int r = 0; r < MS_ROWS; r++) { acc0[r] = b01; acc1[r] = b23; }

        const ulonglong2* wU2 = (const ulonglong2*)wsm;
#pragma unroll
        for (int k = 0; k < 16; k++) {
            ulonglong2 w = wU2[k * 256 + tid];    // LDS.128, conflict-free
#pragma unroll
            for (int r = 0; r < MS_ROWS; r++) {
                unsigned long long sv = sdup[r * 16 + k];  // broadcast
                acc0[r] = fma2(w.x, sv, acc0[r]);
                acc1[r] = fma2(w.y, sv, acc1[r]);
            }
        }
#pragma unroll
        for (int r = 0; r < MS_ROWS; r++) {
            sr[r] += ex2(flo(acc0[r])) + ex2(fhi(acc0[r])) +
                     ex2(flo(acc1[r])) + ex2(fhi(acc1[r]));
        }
    }

    // block sum-reduce per row; alias onto wsm (16KB)
    __syncthreads();
    float* rs = wsm;              // [16][256]
#pragma unroll
    for (int r = 0; r < MS_ROWS; r++) rs[r * 256 + tid] = sr[r];
    for (int step = 128; step > 0; step >>= 1) {
        __syncthreads();
        if (tid < step) {
#pragma unroll
            for (int r = 0; r < MS_ROWS; r++)
                rs[r * 256 + tid] += rs[r * 256 + tid + step];
        }
    }
    __syncthreads();
    if (tid < MS_ROWS) {
        int row = row0 + tid;
        float lse = LN2 * __log2f(rs[tid * 256]);
        float acc = 0.0f;
#pragma unroll
        for (int k = 0; k < 16; k++) acc += g_s[row * 16 + k] * g_w2sum[k];
        out[BATCH + row] = acc * (1.0f / (float)NAGENTS) + g_b2mean - lse;
    }
}

// ---------------------------------------------------------------------------
// launch (9 kernels)
// ---------------------------------------------------------------------------
extern "C" void kernel_launch(void* const* d_in, const int* in_sizes, int n_in,
                              void* d_out, int out_size) {
    const float* x    = (const float*)d_in[0];
    const float* xmsg = (const float*)d_in[1];
    const int*   ei   = (const int*)d_in[2];
    const int*   act  = (const int*)d_in[3];
    const float* c1w  = (const float*)d_in[4];
    const float* c1b  = (const float*)d_in[5];
    const float* c2w  = (const float*)d_in[6];
    const float* c2b  = (const float*)d_in[7];
    const float* fcw  = (const float*)d_in[8];
    const float* fcb  = (const float*)d_in[9];
    const float* muw  = (const float*)d_in[10];
    const float* mub  = (const float*)d_in[11];
    const float* msw  = (const float*)d_in[12];
    const float* msb  = (const float*)d_in[13];
    const float* g1w  = (const float*)d_in[14];
    const float* g1b  = (const float*)d_in[15];
    const float* g2w  = (const float*)d_in[16];
    const float* g2b  = (const float*)d_in[17];
    float* out = (float*)d_out;

    cudaFuncSetAttribute(k_msgout, cudaFuncAttributeMaxDynamicSharedMemorySize,
                         MS_SMEM);

    k_pre<<<579, 256>>>(fcw, c2w, g2w, g2b);
    k_deg<<<NEDGES / 256, 256>>>(ei);

    k_convs<<<BATCH, 256>>>(x, c1w, c1b, c2b);
    k_fc_gemm<<<128, 128>>>();
    k_lgenc<<<256 + NAGENTS / 8, 256>>>(fcb, muw, mub, act, msw, msb, xmsg,
                                        out);

    k_edge1<<<NEDGES / 256, 256>>>(ei, xmsg);
    k_g1s<<<NAGENTS * 16 / 256, 256>>>(g1w, g1b);
    k_edge2<<<NEDGES / 256, 256>>>(ei);

    k_msgout<<<NAGENTS / MS_ROWS, 256, MS_SMEM>>>(g2w, g2b, out);
}

// round 13
// speedup vs baseline: 1.1188x; 1.0298x over previous
#include <cuda_runtime.h>
#include <cuda_bf16.h>
#include <cstdint>

// ---------------------------------------------------------------------------
// Sizes (fixed by the problem)
// ---------------------------------------------------------------------------
#define BATCH    256
#define NAGENTS  8192
#define NEDGES   262144
#define ACT      21

#define L2E 1.4426950408889634f
#define LN2 0.6931471805599453f

// ---------------------------------------------------------------------------
// Scratch (device globals: no allocation allowed)
// ---------------------------------------------------------------------------
__device__ __align__(16) float g_h2t[1024 * BATCH];   // conv2 out, TRANSPOSED [k][m]
__device__ __align__(16) float g_wt[1024 * 512];      // fc_w transposed [k][n]
__device__ __align__(16) float g_w2tp[288 * 65];      // conv2 w, padded transpose [j][oc]
__device__ __align__(16) float g_part[8 * BATCH * 512]; // split-K partials
__device__ float  g_enc[NAGENTS];             // actor_encoding[0]
__device__ float  g_deg[NAGENTS];             // edge-count (no self loop)
__device__ float  g_dinv[NAGENTS];
__device__ __align__(16) float2 g_AB[NAGENTS];  // rank-2 gcn1 aggregates
__device__ __align__(16) float  g_g1[NAGENTS * 16];
__device__ __align__(16) float  g_s[NAGENTS * 16]; // gcn2 input aggregates
__device__ float  g_w2sum[16];
__device__ float  g_b2mean;

// ---------------------------------------------------------------------------
// helpers
// ---------------------------------------------------------------------------
__device__ __forceinline__ unsigned long long fma2(unsigned long long a,
                                                   unsigned long long b,
                                                   unsigned long long c) {
    unsigned long long d;
    asm("fma.rn.f32x2 %0, %1, %2, %3;" : "=l"(d) : "l"(a), "l"(b), "l"(c));
    return d;
}
__device__ __forceinline__ unsigned long long dup2(float v) {
    unsigned u = __float_as_uint(v);
    return ((unsigned long long)u << 32) | (unsigned long long)u;
}
__device__ __forceinline__ unsigned long long pack2(float lo, float hi) {
    return ((unsigned long long)__float_as_uint(hi) << 32) |
           (unsigned long long)__float_as_uint(lo);
}
__device__ __forceinline__ float flo(unsigned long long v) {
    return __uint_as_float((unsigned)v);
}
__device__ __forceinline__ float fhi(unsigned long long v) {
    return __uint_as_float((unsigned)(v >> 32));
}
__device__ __forceinline__ float ex2(float v) {
    float r;
    asm("ex2.approx.ftz.f32 %0, %1;" : "=f"(r) : "f"(v));
    return r;
}
__device__ __forceinline__ void red4(float* p, float a, float b, float c,
                                     float d) {
    asm volatile("red.global.add.v4.f32 [%0], {%1, %2, %3, %4};"
                 :: "l"(p), "f"(a), "f"(b), "f"(c), "f"(d) : "memory");
}
__device__ __forceinline__ void red2(float* p, float a, float b) {
    asm volatile("red.global.add.v2.f32 [%0], {%1, %2};"
                 :: "l"(p), "f"(a), "f"(b) : "memory");
}

// ---------------------------------------------------------------------------
// k_pre: all independent preprocessing in ONE kernel.
//  blocks [0,512)     : transpose fc_w [512][1024] -> g_wt [1024][512]
//  blocks [512,530)   : pad-transpose c2w [64][288] -> g_w2tp [288][65]
//  blocks [530,547)   : colsum(W2) (16) + mean(b2) (1)
//  blocks [547,1571)  : degree atomics (g_deg pre-zeroed by memset;
//                       self-loop +1 folded into rsqrt at consumption)
// ---------------------------------------------------------------------------
__global__ void __launch_bounds__(256) k_pre(const float* __restrict__ fc_w,
                                             const float* __restrict__ c2w,
                                             const float* __restrict__ W2,
                                             const float* __restrict__ b2,
                                             const int* __restrict__ ei) {
    const int bid = blockIdx.x, tid = threadIdx.x;
    if (bid < 512) {
        __shared__ float t[32][33];
        const int bk = bid & 31;   // 32 k-tiles
        const int bn = bid >> 5;   // 16 n-tiles
        const int tx = tid & 31, ty = tid >> 5;  // 32 x 8
#pragma unroll
        for (int i = 0; i < 32; i += 8)
            t[ty + i][tx] = fc_w[(bn * 32 + ty + i) * 1024 + bk * 32 + tx];
        __syncthreads();
#pragma unroll
        for (int i = 0; i < 32; i += 8)
            g_wt[(bk * 32 + ty + i) * 512 + bn * 32 + tx] = t[tx][ty + i];
    } else if (bid < 530) {
        int base = (bid - 512) * 1024;
#pragma unroll
        for (int q = 0; q < 4; q++) {
            int idx = base + q * 256 + tid;
            if (idx < 64 * 288) {
                int oc = idx / 288, j = idx - oc * 288;
                g_w2tp[j * 65 + oc] = c2w[idx];
            }
        }
    } else if (bid < 547) {
        int k = bid - 530;
        __shared__ float red[256];
        const float* src = (k < 16) ? (W2 + k * NAGENTS) : b2;
        float acc = 0.0f;
        for (int j = tid; j < NAGENTS; j += 256) acc += src[j];
        red[tid] = acc;
        __syncthreads();
        for (int s = 128; s; s >>= 1) {
            if (tid < s) red[tid] += red[tid + s];
            __syncthreads();
        }
        if (tid == 0) {
            if (k < 16) g_w2sum[k] = red[0];
            else        g_b2mean  = red[0] * (1.0f / (float)NAGENTS);
        }
    } else {
        int e = (bid - 547) * 256 + tid;
        if (e < NEDGES) atomicAdd(&g_deg[ei[2 * e + 1]], 1.0f);
    }
}

// ---------------------------------------------------------------------------
// Fused conv1+conv2 per batch element. One CTA per batch.
// conv2 weights staged via pure coalesced float4 copy from the pre-padded
// g_w2tp ([j][65] layout -> conflict-free quad-broadcast reads).
// Writes h2 TRANSPOSED directly (g_h2t[k][m]) for the GEMM.
// ---------------------------------------------------------------------------
__global__ void __launch_bounds__(256) k_convs(const float* __restrict__ x,
                                               const float* __restrict__ c1w,
                                               const float* __restrict__ c1b,
                                               const float* __restrict__ c2b) {
    __shared__ float xs[848];
    __shared__ float h1s[1152];
    __shared__ __align__(16) float w2s[288 * 65];
    const int b = blockIdx.x, tid = threadIdx.x;

    // stage: pure float4 copies, no div/mod, coalesced
    {
        const float4* src = (const float4*)g_w2tp;
        float4* dst = (float4*)w2s;
        for (int i = tid; i < (288 * 65) / 4; i += 256) dst[i] = src[i];
    }
    for (int i = tid; i < 845; i += 256) xs[i] = x[b * 845 + i];
    __syncthreads();

    // conv1: 1152 outputs, 4-5 per thread
    for (int idx = tid; idx < 1152; idx += 256) {
        int oc = idx / 36, p = idx % 36;
        int oy = p / 6, ox = p % 6;
        const float* wb = c1w + oc * 45;
        float acc = c1b[oc];
#pragma unroll
        for (int ic = 0; ic < 5; ic++)
#pragma unroll
            for (int ky = 0; ky < 3; ky++)
#pragma unroll
                for (int kx = 0; kx < 3; kx++)
                    acc += xs[ic * 169 + (2 * oy + ky) * 13 + 2 * ox + kx] *
                           wb[ic * 9 + ky * 3 + kx];
        h1s[idx] = fmaxf(acc, 0.0f);
    }
    __syncthreads();

    // conv2: thread -> (oc = tid/4, oy = tid%4), 4 outputs along ox
    const int oc = tid >> 2, oy = tid & 3;
    float bias = c2b[oc];
    float acc[4];
#pragma unroll
    for (int q = 0; q < 4; q++) acc[q] = bias;

#pragma unroll 4
    for (int ic = 0; ic < 32; ic++) {
#pragma unroll
        for (int ky = 0; ky < 3; ky++) {
            const float* row = &h1s[ic * 36 + (oy + ky) * 6];
            float r0 = row[0], r1 = row[1], r2 = row[2];
            float r3 = row[3], r4 = row[4], r5 = row[5];
            const float* wr = &w2s[(ic * 9 + ky * 3) * 65 + oc];
            float w0 = wr[0], w1 = wr[65], w2 = wr[130];
            acc[0] += r0 * w0 + r1 * w1 + r2 * w2;
            acc[1] += r1 * w0 + r2 * w1 + r3 * w2;
            acc[2] += r2 * w0 + r3 * w1 + r4 * w2;
            acc[3] += r3 * w0 + r4 * w1 + r5 * w2;
        }
    }
    int f0 = oc * 16 + oy * 4;
#pragma unroll
    for (int q = 0; q < 4; q++)
        g_h2t[(f0 + q) * BATCH + b] = fmaxf(acc[q], 0.0f);
}

// ---------------------------------------------------------------------------
// fc GEMM: part[ks] += h2t[kslice]^T x wt[kslice].  C = [256 x 512].
// BM=BN=64, split-K=8 (K=128 per CTA, 2 chunks of 64) -> 256 CTAs
// (2 CTAs/SM, 2 warps/SMSP), 128 threads, 8x4 microtile, f32x2.
// ---------------------------------------------------------------------------
__global__ void __launch_bounds__(128) k_fc_gemm() {
    __shared__ float As[64 * 64];   // [k][m]
    __shared__ float Bs[64 * 64];   // [k][n]
    const int bx = blockIdx.x;
    const int ks = bx >> 5;           // 0..7
    const int mt = (bx >> 3) & 3;
    const int nt = bx & 7;
    const int m0 = mt * 64, n0 = nt * 64;
    const int t  = threadIdx.x;
    const int tc = t & 15, tr = t >> 4;   // tc: 4-col group, tr: 8-row group

    unsigned long long acc[4][4];
#pragma unroll
    for (int p = 0; p < 4; p++)
#pragma unroll
        for (int j = 0; j < 4; j++) acc[p][j] = 0ull;

    const float4* A4g = (const float4*)g_h2t;
    const float4* B4g = (const float4*)g_wt;
    float4* As4w = (float4*)As;
    float4* Bs4w = (float4*)Bs;

#pragma unroll
    for (int c = 0; c < 2; c++) {
        int k0 = ks * 128 + c * 64;
        __syncthreads();
#pragma unroll
        for (int j = 0; j < 8; j++) {
            int idx = t + 128 * j;           // 0..1023
            int kk = idx >> 4, q = idx & 15;
            As4w[kk * 16 + q] = A4g[((k0 + kk) * BATCH + m0) / 4 + q];
            Bs4w[kk * 16 + q] = B4g[((k0 + kk) * 512 + n0) / 4 + q];
        }
        __syncthreads();

        const float4* As4 = (const float4*)As;
        const float4* Bs4 = (const float4*)Bs;
#pragma unroll 8
        for (int k = 0; k < 64; k++) {
            float4 a0 = As4[k * 16 + tr * 2];
            float4 a1 = As4[k * 16 + tr * 2 + 1];
            float4 bv = Bs4[k * 16 + tc];
            unsigned long long ap[4] = {pack2(a0.x, a0.y), pack2(a0.z, a0.w),
                                        pack2(a1.x, a1.y), pack2(a1.z, a1.w)};
            unsigned long long bd[4] = {dup2(bv.x), dup2(bv.y),
                                        dup2(bv.z), dup2(bv.w)};
#pragma unroll
            for (int p = 0; p < 4; p++)
#pragma unroll
                for (int j = 0; j < 4; j++)
                    acc[p][j] = fma2(ap[p], bd[j], acc[p][j]);
        }
    }

    float* outp = g_part + ks * (BATCH * 512);
#pragma unroll
    for (int p = 0; p < 4; p++) {
        int rlo = m0 + tr * 8 + 2 * p;
        float4 vlo = make_float4(flo(acc[p][0]), flo(acc[p][1]),
                                 flo(acc[p][2]), flo(acc[p][3]));
        float4 vhi = make_float4(fhi(acc[p][0]), fhi(acc[p][1]),
                                 fhi(acc[p][2]), fhi(acc[p][3]));
        *(float4*)(outp + rlo * 512 + n0 + tc * 4) = vlo;
        *(float4*)(outp + (rlo + 1) * 512 + n0 + tc * 4) = vhi;
    }
}

// ---------------------------------------------------------------------------
// Reconstruct one hidden row from the 8 split-K slabs + bias + relu into smem.
// ---------------------------------------------------------------------------
__device__ __forceinline__ void load_hidden_row(float* hs, int row,
                                                const float* __restrict__ fcb,
                                                int tid) {
    float2 acc = make_float2(0.0f, 0.0f);
#pragma unroll
    for (int s = 0; s < 8; s++) {
        float2 v = ((const float2*)(g_part + s * (BATCH * 512) + row * 512))[tid];
        acc.x += v.x;
        acc.y += v.y;
    }
    float2 bias = ((const float2*)fcb)[tid];
    ((float2*)hs)[tid] = make_float2(fmaxf(acc.x + bias.x, 0.0f),
                                     fmaxf(acc.y + bias.y, 0.0f));
}

// ---------------------------------------------------------------------------
// k_lgenc: fused logits head + actor-encoding + gcn node prep.
//  blocks [0,256):   logits/log_prob/entropy/action for batch row bid
//  blocks [256,1280): enc[j] (8 j per block) + dinv[j] + self-loop AB[j]
// Output layout: [action(256) | msg_out(8192) | log_prob(256) | entropy(256)]
// ---------------------------------------------------------------------------
__global__ void __launch_bounds__(256) k_lgenc(const float* __restrict__ fcb,
                                               const float* __restrict__ muw,
                                               const float* __restrict__ mub,
                                               const int* __restrict__ action,
                                               const float* __restrict__ msw,
                                               const float* __restrict__ msb,
                                               const float* __restrict__ xm,
                                               float* __restrict__ out) {
    __shared__ float hs[512];
    __shared__ float lg[24];
    const int bid = blockIdx.x, tid = threadIdx.x;
    const int wid = tid >> 5, lane = tid & 31;

    if (bid < 256) {
        load_hidden_row(hs, bid, fcb, tid);
        __syncthreads();

        const float4* h4 = (const float4*)hs;
        for (int a = wid; a < ACT; a += 8) {
            const float4* wr = (const float4*)(muw + a * 512);
            float acc = 0.0f;
#pragma unroll
            for (int i = 0; i < 4; i++) {
                float4 w = wr[lane + i * 32];
                float4 h = h4[lane + i * 32];
                acc += w.x * h.x + w.y * h.y + w.z * h.z + w.w * h.w;
            }
#pragma unroll
            for (int o = 16; o; o >>= 1)
                acc += __shfl_xor_sync(0xffffffffu, acc, o);
            if (lane == 0) lg[a] = acc + mub[a];
        }
        __syncthreads();

        if (wid == 0) {
            float l = (lane < ACT) ? lg[lane] : -3.4e38f;
            float m = l;
#pragma unroll
            for (int o = 16; o; o >>= 1)
                m = fmaxf(m, __shfl_xor_sync(0xffffffffu, m, o));
            float e  = (lane < ACT) ? __expf(l - m) : 0.0f;
            float el = (lane < ACT) ? e * l : 0.0f;
            float se = e, sel = el;
#pragma unroll
            for (int o = 16; o; o >>= 1) {
                se  += __shfl_xor_sync(0xffffffffu, se, o);
                sel += __shfl_xor_sync(0xffffffffu, sel, o);
            }
            int a = action[bid];
            float la = __shfl_sync(0xffffffffu, l, a);
            if (lane == 0) {
                float lse = m + __logf(se);
                out[BATCH + NAGENTS + bid]     = la - lse;        // log_prob
                out[2 * BATCH + NAGENTS + bid] = lse - sel / se;  // entropy
                out[bid] = (float)a;                              // action
            }
        }
    } else {
        load_hidden_row(hs, 0, fcb, tid);
        __syncthreads();

        const int j = (bid - 256) * 8 + wid;
        const float4* w4 = (const float4*)(msw + j * 512);
        const float4* h4 = (const float4*)hs;
        float acc = 0.0f;
#pragma unroll
        for (int i = 0; i < 4; i++) {
            float4 w = w4[lane + i * 32];
            float4 h = h4[lane + i * 32];
            acc += w.x * h.x + w.y * h.y + w.z * h.z + w.w * h.w;
        }
#pragma unroll
        for (int o = 16; o; o >>= 1) acc += __shfl_xor_sync(0xffffffffu, acc, o);
        if (lane == 0) {
            float e = acc + msb[j];
            g_enc[j] = e;
            float dv = rsqrtf(g_deg[j] + 1.0f);   // +1 = self loop
            g_dinv[j] = dv;
            float d2 = dv * dv;                   // self-loop norm
            g_AB[j] = make_float2(d2 * xm[j], d2 * e);
        }
    }
}

// ---------------------------------------------------------------------------
// GCN edge aggregation
// ---------------------------------------------------------------------------
__global__ void k_edge1(const int* __restrict__ ei,
                        const float* __restrict__ xm) {
    int e = blockIdx.x * 256 + threadIdx.x;
    if (e >= NEDGES) return;
    int s = ei[2 * e], d = ei[2 * e + 1];
    float nrm = g_dinv[s] * g_dinv[d];
    red2((float*)&g_AB[d], nrm * xm[s], nrm * g_enc[s]);
}
// g1 = relu(AB @ W1 + b1); s initialized with the self-loop term d^2 * g1
__global__ void k_g1s(const float* __restrict__ w1,
                      const float* __restrict__ b1) {
    int idx = blockIdx.x * 256 + threadIdx.x;
    if (idx >= NAGENTS * 16) return;
    int i = idx >> 4, k = idx & 15;
    float2 ab = g_AB[i];
    float v = fmaxf(ab.x * w1[k] + ab.y * w1[16 + k] + b1[k], 0.0f);
    g_g1[idx] = v;
    float dv = g_dinv[i];
    g_s[idx] = dv * dv * v;
}
__global__ void k_edge2(const int* __restrict__ ei) {
    int e = blockIdx.x * 256 + threadIdx.x;
    if (e >= NEDGES) return;
    int s = ei[2 * e], d = ei[2 * e + 1];
    float nrm = g_dinv[s] * g_dinv[d];
    const float4* g1r = (const float4*)(g_g1 + s * 16);
    float* sd = g_s + d * 16;
#pragma unroll
    for (int q = 0; q < 4; q++) {
        float4 v = g1r[q];
        red4(sd + q * 4, nrm * v.x, nrm * v.y, nrm * v.z, nrm * v.w);
    }
}

// ---------------------------------------------------------------------------
// K12: msg_out[i] = mean_j(g_ij) - lse_j(g_ij) with g_ij = s[i].W2[:,j]+b2[j].
// 16 rows/CTA, W2 streamed in 16x1024 SMEM chunks, f32x2 FMA.
// log2-domain accumulation (s, b2 pre-scaled by log2 e) -> raw ex2, no
// max-tracking needed (|g| bounded analytically far below overflow).
// ---------------------------------------------------------------------------
#define MS_CHUNK 1024
#define MS_ROWS  16
#define MS_SMEM  (16 * MS_CHUNK * 4 + MS_ROWS * 16 * 8)

__global__ void __launch_bounds__(256) k_msgout(const float* __restrict__ W2,
                                                const float* __restrict__ b2,
                                                float* __restrict__ out) {
    extern __shared__ char smraw[];
    float* wsm = (float*)smraw;                                    // 16*1024 f
    unsigned long long* sdup =
        (unsigned long long*)(smraw + 16 * MS_CHUNK * 4);          // 256 u64

    const int tid  = threadIdx.x;
    const int row0 = blockIdx.x * MS_ROWS;

    {   // duplicated, log2e-scaled s values for f32x2 broadcast
        int r = tid >> 4, k = tid & 15;
        sdup[tid] = dup2(g_s[(row0 + r) * 16 + k] * L2E);
    }

    float sr[MS_ROWS];
#pragma unroll
    for (int r = 0; r < MS_ROWS; r++) sr[r] = 0.0f;

    const float4* gw4 = (const float4*)W2;

    for (int chunk = 0; chunk < NAGENTS / MS_CHUNK; chunk++) {
        int base = chunk * MS_CHUNK;
        __syncthreads();
#pragma unroll
        for (int k = 0; k < 16; k++)
            ((float4*)wsm)[k * 256 + tid] = gw4[(k * NAGENTS + base) / 4 + tid];
        float4 bb = ((const float4*)(b2 + base))[tid];
        __syncthreads();

        unsigned long long acc0[MS_ROWS], acc1[MS_ROWS];
        unsigned long long b01 = pack2(bb.x * L2E, bb.y * L2E);
        unsigned long long b23 = pack2(bb.z * L2E, bb.w * L2E);
#pragma unroll
        for (int r = 0; r < MS_ROWS; r++) { acc0[r] = b01; acc1[r] = b23; }

        const ulonglong2* wU2 = (const ulonglong2*)wsm;
#pragma unroll
        for (int k = 0; k < 16; k++) {
            ulonglong2 w = wU2[k * 256 + tid];    // LDS.128, conflict-free
#pragma unroll
            for (int r = 0; r < MS_ROWS; r++) {
                unsigned long long sv = sdup[r * 16 + k];  // broadcast
                acc0[r] = fma2(w.x, sv, acc0[r]);
                acc1[r] = fma2(w.y, sv, acc1[r]);
            }
        }
#pragma unroll
        for (int r = 0; r < MS_ROWS; r++) {
            sr[r] += ex2(flo(acc0[r])) + ex2(fhi(acc0[r])) +
                     ex2(flo(acc1[r])) + ex2(fhi(acc1[r]));
        }
    }

    // block sum-reduce per row; alias onto wsm (16KB)
    __syncthreads();
    float* rs = wsm;              // [16][256]
#pragma unroll
    for (int r = 0; r < MS_ROWS; r++) rs[r * 256 + tid] = sr[r];
    for (int step = 128; step > 0; step >>= 1) {
        __syncthreads();
        if (tid < step) {
#pragma unroll
            for (int r = 0; r < MS_ROWS; r++)
                rs[r * 256 + tid] += rs[r * 256 + tid + step];
        }
    }
    __syncthreads();
    if (tid < MS_ROWS) {
        int row = row0 + tid;
        float lse = LN2 * __log2f(rs[tid * 256]);
        float acc = 0.0f;
#pragma unroll
        for (int k = 0; k < 16; k++) acc += g_s[row * 16 + k] * g_w2sum[k];
        out[BATCH + row] = acc * (1.0f / (float)NAGENTS) + g_b2mean - lse;
    }
}

// ---------------------------------------------------------------------------
// launch (8 kernels + 1 memset)
// ---------------------------------------------------------------------------
extern "C" void kernel_launch(void* const* d_in, const int* in_sizes, int n_in,
                              void* d_out, int out_size) {
    const float* x    = (const float*)d_in[0];
    const float* xmsg = (const float*)d_in[1];
    const int*   ei   = (const int*)d_in[2];
    const int*   act  = (const int*)d_in[3];
    const float* c1w  = (const float*)d_in[4];
    const float* c1b  = (const float*)d_in[5];
    const float* c2w  = (const float*)d_in[6];
    const float* c2b  = (const float*)d_in[7];
    const float* fcw  = (const float*)d_in[8];
    const float* fcb  = (const float*)d_in[9];
    const float* muw  = (const float*)d_in[10];
    const float* mub  = (const float*)d_in[11];
    const float* msw  = (const float*)d_in[12];
    const float* msb  = (const float*)d_in[13];
    const float* g1w  = (const float*)d_in[14];
    const float* g1b  = (const float*)d_in[15];
    const float* g2w  = (const float*)d_in[16];
    const float* g2b  = (const float*)d_in[17];
    float* out = (float*)d_out;

    cudaFuncSetAttribute(k_msgout, cudaFuncAttributeMaxDynamicSharedMemorySize,
                         MS_SMEM);

    void* degp;
    cudaGetSymbolAddress(&degp, g_deg);
    cudaMemsetAsync(degp, 0, NAGENTS * sizeof(float));

    k_pre<<<547 + NEDGES / 256, 256>>>(fcw, c2w, g2w, g2b, ei);

    k_convs<<<BATCH, 256>>>(x, c1w, c1b, c2b);
    k_fc_gemm<<<256, 128>>>();
    k_lgenc<<<256 + NAGENTS / 8, 256>>>(fcb, muw, mub, act, msw, msb, xmsg,
                                        out);

    k_edge1<<<NEDGES / 256, 256>>>(ei, xmsg);
    k_g1s<<<NAGENTS * 16 / 256, 256>>>(g1w, g1b);
    k_edge2<<<NEDGES / 256, 256>>>(ei);

    k_msgout<<<NAGENTS / MS_ROWS, 256, MS_SMEM>>>(g2w, g2b, out);
}

// round 14
// speedup vs baseline: 1.1342x; 1.0137x over previous
#include <cuda_runtime.h>
#include <cuda_bf16.h>
#include <cstdint>

// ---------------------------------------------------------------------------
// Sizes (fixed by the problem)
// ---------------------------------------------------------------------------
#define BATCH    256
#define NAGENTS  8192
#define NEDGES   262144
#define ACT      21

#define L2E 1.4426950408889634f
#define LN2 0.6931471805599453f

// ---------------------------------------------------------------------------
// Scratch (device globals: no allocation allowed)
// ---------------------------------------------------------------------------
__device__ __align__(16) float g_h2t[1024 * BATCH];   // conv2 out, TRANSPOSED [k][m]
__device__ __align__(16) float g_wt[1024 * 512];      // fc_w transposed [k][n]
__device__ __align__(16) float g_w2tp[288 * 65];      // conv2 w, padded transpose [j][oc]
__device__ __align__(16) float g_part[16 * BATCH * 512]; // split-K partials
__device__ float  g_enc[NAGENTS];             // actor_encoding[0]
__device__ float  g_deg[NAGENTS];             // edge-count (no self loop)
__device__ float  g_dinv[NAGENTS];
__device__ __align__(16) float2 g_AB[NAGENTS];  // rank-2 gcn1 aggregates
__device__ __align__(16) float  g_g1[NAGENTS * 16];
__device__ __align__(16) float  g_s[NAGENTS * 16]; // gcn2 input aggregates
__device__ float  g_w2sum[16];
__device__ float  g_b2mean;

// ---------------------------------------------------------------------------
// helpers
// ---------------------------------------------------------------------------
__device__ __forceinline__ unsigned long long fma2(unsigned long long a,
                                                   unsigned long long b,
                                                   unsigned long long c) {
    unsigned long long d;
    asm("fma.rn.f32x2 %0, %1, %2, %3;" : "=l"(d) : "l"(a), "l"(b), "l"(c));
    return d;
}
__device__ __forceinline__ unsigned long long dup2(float v) {
    unsigned u = __float_as_uint(v);
    return ((unsigned long long)u << 32) | (unsigned long long)u;
}
__device__ __forceinline__ unsigned long long pack2(float lo, float hi) {
    return ((unsigned long long)__float_as_uint(hi) << 32) |
           (unsigned long long)__float_as_uint(lo);
}
__device__ __forceinline__ float flo(unsigned long long v) {
    return __uint_as_float((unsigned)v);
}
__device__ __forceinline__ float fhi(unsigned long long v) {
    return __uint_as_float((unsigned)(v >> 32));
}
__device__ __forceinline__ float ex2(float v) {
    float r;
    asm("ex2.approx.ftz.f32 %0, %1;" : "=f"(r) : "f"(v));
    return r;
}
__device__ __forceinline__ void red4(float* p, float a, float b, float c,
                                     float d) {
    asm volatile("red.global.add.v4.f32 [%0], {%1, %2, %3, %4};"
                 :: "l"(p), "f"(a), "f"(b), "f"(c), "f"(d) : "memory");
}
__device__ __forceinline__ void red2(float* p, float a, float b) {
    asm volatile("red.global.add.v2.f32 [%0], {%1, %2};"
                 :: "l"(p), "f"(a), "f"(b) : "memory");
}

// ---------------------------------------------------------------------------
// k_pre: all independent preprocessing in ONE kernel.
//  blocks [0,512)     : transpose fc_w [512][1024] -> g_wt [1024][512]
//  blocks [512,530)   : pad-transpose c2w [64][288] -> g_w2tp [288][65]
//  blocks [530,547)   : colsum(W2) (16) + mean(b2) (1)
//  blocks [547,1571)  : degree atomics (g_deg pre-zeroed by memset;
//                       self-loop +1 folded into rsqrt at consumption)
// ---------------------------------------------------------------------------
__global__ void __launch_bounds__(256) k_pre(const float* __restrict__ fc_w,
                                             const float* __restrict__ c2w,
                                             const float* __restrict__ W2,
                                             const float* __restrict__ b2,
                                             const int* __restrict__ ei) {
    const int bid = blockIdx.x, tid = threadIdx.x;
    if (bid < 512) {
        __shared__ float t[32][33];
        const int bk = bid & 31;   // 32 k-tiles
        const int bn = bid >> 5;   // 16 n-tiles
        const int tx = tid & 31, ty = tid >> 5;  // 32 x 8
#pragma unroll
        for (int i = 0; i < 32; i += 8)
            t[ty + i][tx] = fc_w[(bn * 32 + ty + i) * 1024 + bk * 32 + tx];
        __syncthreads();
#pragma unroll
        for (int i = 0; i < 32; i += 8)
            g_wt[(bk * 32 + ty + i) * 512 + bn * 32 + tx] = t[tx][ty + i];
    } else if (bid < 530) {
        int base = (bid - 512) * 1024;
#pragma unroll
        for (int q = 0; q < 4; q++) {
            int idx = base + q * 256 + tid;
            if (idx < 64 * 288) {
                int oc = idx / 288, j = idx - oc * 288;
                g_w2tp[j * 65 + oc] = c2w[idx];
            }
        }
    } else if (bid < 547) {
        int k = bid - 530;
        __shared__ float red[256];
        const float* src = (k < 16) ? (W2 + k * NAGENTS) : b2;
        float acc = 0.0f;
        for (int j = tid; j < NAGENTS; j += 256) acc += src[j];
        red[tid] = acc;
        __syncthreads();
        for (int s = 128; s; s >>= 1) {
            if (tid < s) red[tid] += red[tid + s];
            __syncthreads();
        }
        if (tid == 0) {
            if (k < 16) g_w2sum[k] = red[0];
            else        g_b2mean  = red[0] * (1.0f / (float)NAGENTS);
        }
    } else {
        int e = (bid - 547) * 256 + tid;
        if (e < NEDGES) atomicAdd(&g_deg[ei[2 * e + 1]], 1.0f);
    }
}

// ---------------------------------------------------------------------------
// Fused conv1+conv2 per batch element. One CTA per batch.
// conv2 weights staged via pure coalesced float4 copy from the pre-padded
// g_w2tp ([j][65] layout -> conflict-free quad-broadcast reads).
// Writes h2 TRANSPOSED directly (g_h2t[k][m]) for the GEMM.
// ---------------------------------------------------------------------------
__global__ void __launch_bounds__(256) k_convs(const float* __restrict__ x,
                                               const float* __restrict__ c1w,
                                               const float* __restrict__ c1b,
                                               const float* __restrict__ c2b) {
    __shared__ float xs[848];
    __shared__ float h1s[1152];
    __shared__ __align__(16) float w2s[288 * 65];
    const int b = blockIdx.x, tid = threadIdx.x;

    // stage: pure float4 copies, no div/mod, coalesced
    {
        const float4* src = (const float4*)g_w2tp;
        float4* dst = (float4*)w2s;
        for (int i = tid; i < (288 * 65) / 4; i += 256) dst[i] = src[i];
    }
    for (int i = tid; i < 845; i += 256) xs[i] = x[b * 845 + i];
    __syncthreads();

    // conv1: 1152 outputs, 4-5 per thread
    for (int idx = tid; idx < 1152; idx += 256) {
        int oc = idx / 36, p = idx % 36;
        int oy = p / 6, ox = p % 6;
        const float* wb = c1w + oc * 45;
        float acc = c1b[oc];
#pragma unroll
        for (int ic = 0; ic < 5; ic++)
#pragma unroll
            for (int ky = 0; ky < 3; ky++)
#pragma unroll
                for (int kx = 0; kx < 3; kx++)
                    acc += xs[ic * 169 + (2 * oy + ky) * 13 + 2 * ox + kx] *
                           wb[ic * 9 + ky * 3 + kx];
        h1s[idx] = fmaxf(acc, 0.0f);
    }
    __syncthreads();

    // conv2: thread -> (oc = tid/4, oy = tid%4), 4 outputs along ox
    const int oc = tid >> 2, oy = tid & 3;
    float bias = c2b[oc];
    float acc[4];
#pragma unroll
    for (int q = 0; q < 4; q++) acc[q] = bias;

#pragma unroll 4
    for (int ic = 0; ic < 32; ic++) {
#pragma unroll
        for (int ky = 0; ky < 3; ky++) {
            const float* row = &h1s[ic * 36 + (oy + ky) * 6];
            float r0 = row[0], r1 = row[1], r2 = row[2];
            float r3 = row[3], r4 = row[4], r5 = row[5];
            const float* wr = &w2s[(ic * 9 + ky * 3) * 65 + oc];
            float w0 = wr[0], w1 = wr[65], w2 = wr[130];
            acc[0] += r0 * w0 + r1 * w1 + r2 * w2;
            acc[1] += r1 * w0 + r2 * w1 + r3 * w2;
            acc[2] += r2 * w0 + r3 * w1 + r4 * w2;
            acc[3] += r3 * w0 + r4 * w1 + r5 * w2;
        }
    }
    int f0 = oc * 16 + oy * 4;
#pragma unroll
    for (int q = 0; q < 4; q++)
        g_h2t[(f0 + q) * BATCH + b] = fmaxf(acc[q], 0.0f);
}

// ---------------------------------------------------------------------------
// fc GEMM: part[ks] += h2t[kslice]^T x wt[kslice].  C = [256 x 512].
// BM=BN=64, split-K=16 (K=64 per CTA, single chunk) -> 512 CTAs
// (~3.5 CTAs/SM), 128 threads, 8x4 microtile, f32x2.
// ---------------------------------------------------------------------------
__global__ void __launch_bounds__(128) k_fc_gemm() {
    __shared__ float As[64 * 64];   // [k][m]
    __shared__ float Bs[64 * 64];   // [k][n]
    const int bx = blockIdx.x;
    const int ks = bx >> 5;           // 0..15
    const int mt = (bx >> 3) & 3;
    const int nt = bx & 7;
    const int m0 = mt * 64, n0 = nt * 64;
    const int t  = threadIdx.x;
    const int tc = t & 15, tr = t >> 4;   // tc: 4-col group, tr: 8-row group
    const int k0 = ks * 64;

    unsigned long long acc[4][4];
#pragma unroll
    for (int p = 0; p < 4; p++)
#pragma unroll
        for (int j = 0; j < 4; j++) acc[p][j] = 0ull;

    const float4* A4g = (const float4*)g_h2t;
    const float4* B4g = (const float4*)g_wt;
    float4* As4w = (float4*)As;
    float4* Bs4w = (float4*)Bs;

#pragma unroll
    for (int j = 0; j < 8; j++) {
        int idx = t + 128 * j;           // 0..1023
        int kk = idx >> 4, q = idx & 15;
        As4w[kk * 16 + q] = A4g[((k0 + kk) * BATCH + m0) / 4 + q];
        Bs4w[kk * 16 + q] = B4g[((k0 + kk) * 512 + n0) / 4 + q];
    }
    __syncthreads();

    const float4* As4 = (const float4*)As;
    const float4* Bs4 = (const float4*)Bs;
#pragma unroll 8
    for (int k = 0; k < 64; k++) {
        float4 a0 = As4[k * 16 + tr * 2];
        float4 a1 = As4[k * 16 + tr * 2 + 1];
        float4 bv = Bs4[k * 16 + tc];
        unsigned long long ap[4] = {pack2(a0.x, a0.y), pack2(a0.z, a0.w),
                                    pack2(a1.x, a1.y), pack2(a1.z, a1.w)};
        unsigned long long bd[4] = {dup2(bv.x), dup2(bv.y),
                                    dup2(bv.z), dup2(bv.w)};
#pragma unroll
        for (int p = 0; p < 4; p++)
#pragma unroll
            for (int j = 0; j < 4; j++)
                acc[p][j] = fma2(ap[p], bd[j], acc[p][j]);
    }

    float* outp = g_part + ks * (BATCH * 512);
#pragma unroll
    for (int p = 0; p < 4; p++) {
        int rlo = m0 + tr * 8 + 2 * p;
        float4 vlo = make_float4(flo(acc[p][0]), flo(acc[p][1]),
                                 flo(acc[p][2]), flo(acc[p][3]));
        float4 vhi = make_float4(fhi(acc[p][0]), fhi(acc[p][1]),
                                 fhi(acc[p][2]), fhi(acc[p][3]));
        *(float4*)(outp + rlo * 512 + n0 + tc * 4) = vlo;
        *(float4*)(outp + (rlo + 1) * 512 + n0 + tc * 4) = vhi;
    }
}

// ---------------------------------------------------------------------------
// Reconstruct one hidden row from the 16 split-K slabs + bias + relu into smem.
// ---------------------------------------------------------------------------
__device__ __forceinline__ void load_hidden_row(float* hs, int row,
                                                const float* __restrict__ fcb,
                                                int tid) {
    float2 acc = make_float2(0.0f, 0.0f);
#pragma unroll
    for (int s = 0; s < 16; s++) {
        float2 v = ((const float2*)(g_part + s * (BATCH * 512) + row * 512))[tid];
        acc.x += v.x;
        acc.y += v.y;
    }
    float2 bias = ((const float2*)fcb)[tid];
    ((float2*)hs)[tid] = make_float2(fmaxf(acc.x + bias.x, 0.0f),
                                     fmaxf(acc.y + bias.y, 0.0f));
}

// ---------------------------------------------------------------------------
// k_lgenc: fused logits head + actor-encoding + gcn node prep.
//  blocks [0,256):   logits/log_prob/entropy/action for batch row bid
//  blocks [256,768): enc[j] (16 j per block, 2 per warp for MLP=8)
//                    + dinv[j] + self-loop AB[j]
// Output layout: [action(256) | msg_out(8192) | log_prob(256) | entropy(256)]
// ---------------------------------------------------------------------------
__global__ void __launch_bounds__(256) k_lgenc(const float* __restrict__ fcb,
                                               const float* __restrict__ muw,
                                               const float* __restrict__ mub,
                                               const int* __restrict__ action,
                                               const float* __restrict__ msw,
                                               const float* __restrict__ msb,
                                               const float* __restrict__ xm,
                                               float* __restrict__ out) {
    __shared__ float hs[512];
    __shared__ float lg[24];
    const int bid = blockIdx.x, tid = threadIdx.x;
    const int wid = tid >> 5, lane = tid & 31;

    if (bid < 256) {
        load_hidden_row(hs, bid, fcb, tid);
        __syncthreads();

        const float4* h4 = (const float4*)hs;
        for (int a = wid; a < ACT; a += 8) {
            const float4* wr = (const float4*)(muw + a * 512);
            float acc = 0.0f;
#pragma unroll
            for (int i = 0; i < 4; i++) {
                float4 w = wr[lane + i * 32];
                float4 h = h4[lane + i * 32];
                acc += w.x * h.x + w.y * h.y + w.z * h.z + w.w * h.w;
            }
#pragma unroll
            for (int o = 16; o; o >>= 1)
                acc += __shfl_xor_sync(0xffffffffu, acc, o);
            if (lane == 0) lg[a] = acc + mub[a];
        }
        __syncthreads();

        if (wid == 0) {
            float l = (lane < ACT) ? lg[lane] : -3.4e38f;
            float m = l;
#pragma unroll
            for (int o = 16; o; o >>= 1)
                m = fmaxf(m, __shfl_xor_sync(0xffffffffu, m, o));
            float e  = (lane < ACT) ? __expf(l - m) : 0.0f;
            float el = (lane < ACT) ? e * l : 0.0f;
            float se = e, sel = el;
#pragma unroll
            for (int o = 16; o; o >>= 1) {
                se  += __shfl_xor_sync(0xffffffffu, se, o);
                sel += __shfl_xor_sync(0xffffffffu, sel, o);
            }
            int a = action[bid];
            float la = __shfl_sync(0xffffffffu, l, a);
            if (lane == 0) {
                float lse = m + __logf(se);
                out[BATCH + NAGENTS + bid]     = la - lse;        // log_prob
                out[2 * BATCH + NAGENTS + bid] = lse - sel / se;  // entropy
                out[bid] = (float)a;                              // action
            }
        }
    } else {
        load_hidden_row(hs, 0, fcb, tid);
        __syncthreads();

        // two agents per warp: doubles independent LDGs in flight
        const int j0 = (bid - 256) * 16 + wid * 2;
        const float4* wa4 = (const float4*)(msw + j0 * 512);
        const float4* wb4 = (const float4*)(msw + (j0 + 1) * 512);
        const float4* h4  = (const float4*)hs;
        float acca = 0.0f, accb = 0.0f;
#pragma unroll
        for (int i = 0; i < 4; i++) {
            float4 wa = wa4[lane + i * 32];
            float4 wb = wb4[lane + i * 32];
            float4 h  = h4[lane + i * 32];
            acca += wa.x * h.x + wa.y * h.y + wa.z * h.z + wa.w * h.w;
            accb += wb.x * h.x + wb.y * h.y + wb.z * h.z + wb.w * h.w;
        }
#pragma unroll
        for (int o = 16; o; o >>= 1) {
            acca += __shfl_xor_sync(0xffffffffu, acca, o);
            accb += __shfl_xor_sync(0xffffffffu, accb, o);
        }
        if (lane == 0) {
#pragma unroll
            for (int q = 0; q < 2; q++) {
                int j = j0 + q;
                float e = (q ? accb : acca) + msb[j];
                g_enc[j] = e;
                float dv = rsqrtf(g_deg[j] + 1.0f);   // +1 = self loop
                g_dinv[j] = dv;
                float d2 = dv * dv;                   // self-loop norm
                g_AB[j] = make_float2(d2 * xm[j], d2 * e);
            }
        }
    }
}

// ---------------------------------------------------------------------------
// GCN edge aggregation
// ---------------------------------------------------------------------------
__global__ void k_edge1(const int* __restrict__ ei,
                        const float* __restrict__ xm) {
    int e = blockIdx.x * 256 + threadIdx.x;
    if (e >= NEDGES) return;
    int s = ei[2 * e], d = ei[2 * e + 1];
    float nrm = g_dinv[s] * g_dinv[d];
    red2((float*)&g_AB[d], nrm * xm[s], nrm * g_enc[s]);
}
// g1 = relu(AB @ W1 + b1); s initialized with the self-loop term d^2 * g1
__global__ void k_g1s(const float* __restrict__ w1,
                      const float* __restrict__ b1) {
    int idx = blockIdx.x * 256 + threadIdx.x;
    if (idx >= NAGENTS * 16) return;
    int i = idx >> 4, k = idx & 15;
    float2 ab = g_AB[i];
    float v = fmaxf(ab.x * w1[k] + ab.y * w1[16 + k] + b1[k], 0.0f);
    g_g1[idx] = v;
    float dv = g_dinv[i];
    g_s[idx] = dv * dv * v;
}
__global__ void k_edge2(const int* __restrict__ ei) {
    int e = blockIdx.x * 256 + threadIdx.x;
    if (e >= NEDGES) return;
    int s = ei[2 * e], d = ei[2 * e + 1];
    float nrm = g_dinv[s] * g_dinv[d];
    const float4* g1r = (const float4*)(g_g1 + s * 16);
    float* sd = g_s + d * 16;
#pragma unroll
    for (int q = 0; q < 4; q++) {
        float4 v = g1r[q];
        red4(sd + q * 4, nrm * v.x, nrm * v.y, nrm * v.z, nrm * v.w);
    }
}

// ---------------------------------------------------------------------------
// K12: msg_out[i] = mean_j(g_ij) - lse_j(g_ij) with g_ij = s[i].W2[:,j]+b2[j].
// 16 rows/CTA, W2 streamed in 16x1024 SMEM chunks, f32x2 FMA.
// log2-domain accumulation (s, b2 pre-scaled by log2 e) -> raw ex2, no
// max-tracking needed (|g| bounded analytically far below overflow).
// ---------------------------------------------------------------------------
#define MS_CHUNK 1024
#define MS_ROWS  16
#define MS_SMEM  (16 * MS_CHUNK * 4 + MS_ROWS * 16 * 8)

__global__ void __launch_bounds__(256) k_msgout(const float* __restrict__ W2,
                                                const float* __restrict__ b2,
                                                float* __restrict__ out) {
    extern __shared__ char smraw[];
    float* wsm = (float*)smraw;                                    // 16*1024 f
    unsigned long long* sdup =
        (unsigned long long*)(smraw + 16 * MS_CHUNK * 4);          // 256 u64

    const int tid  = threadIdx.x;
    const int row0 = blockIdx.x * MS_ROWS;

    {   // duplicated, log2e-scaled s values for f32x2 broadcast
        int r = tid >> 4, k = tid & 15;
        sdup[tid] = dup2(g_s[(row0 + r) * 16 + k] * L2E);
    }

    float sr[MS_ROWS];
#pragma unroll
    for (int r = 0; r < MS_ROWS; r++) sr[r] = 0.0f;

    const float4* gw4 = (const float4*)W2;

    for (int chunk = 0; chunk < NAGENTS / MS_CHUNK; chunk++) {
        int base = chunk * MS_CHUNK;
        __syncthreads();
#pragma unroll
        for (int k = 0; k < 16; k++)
            ((float4*)wsm)[k * 256 + tid] = gw4[(k * NAGENTS + base) / 4 + tid];
        float4 bb = ((const float4*)(b2 + base))[tid];
        __syncthreads();

        unsigned long long acc0[MS_ROWS], acc1[MS_ROWS];
        unsigned long long b01 = pack2(bb.x * L2E, bb.y * L2E);
        unsigned long long b23 = pack2(bb.z * L2E, bb.w * L2E);
#pragma unroll
        for (int r = 0; r < MS_ROWS; r++) { acc0[r] = b01; acc1[r] = b23; }

        const ulonglong2* wU2 = (const ulonglong2*)wsm;
#pragma unroll
        for (int k = 0; k < 16; k++) {
            ulonglong2 w = wU2[k * 256 + tid];    // LDS.128, conflict-free
#pragma unroll
            for (int r = 0; r < MS_ROWS; r++) {
                unsigned long long sv = sdup[r * 16 + k];  // broadcast
                acc0[r] = fma2(w.x, sv, acc0[r]);
                acc1[r] = fma2(w.y, sv, acc1[r]);
            }
        }
#pragma unroll
        for (int r = 0; r < MS_ROWS; r++) {
            sr[r] += ex2(flo(acc0[r])) + ex2(fhi(acc0[r])) +
                     ex2(flo(acc1[r])) + ex2(fhi(acc1[r]));
        }
    }

    // block sum-reduce per row; alias onto wsm (16KB)
    __syncthreads();
    float* rs = wsm;              // [16][256]
#pragma unroll
    for (int r = 0; r < MS_ROWS; r++) rs[r * 256 + tid] = sr[r];
    for (int step = 128; step > 0; step >>= 1) {
        __syncthreads();
        if (tid < step) {
#pragma unroll
            for (int r = 0; r < MS_ROWS; r++)
                rs[r * 256 + tid] += rs[r * 256 + tid + step];
        }
    }
    __syncthreads();
    if (tid < MS_ROWS) {
        int row = row0 + tid;
        float lse = LN2 * __log2f(rs[tid * 256]);
        float acc = 0.0f;
#pragma unroll
        for (int k = 0; k < 16; k++) acc += g_s[row * 16 + k] * g_w2sum[k];
        out[BATCH + row] = acc * (1.0f / (float)NAGENTS) + g_b2mean - lse;
    }
}

// ---------------------------------------------------------------------------
// launch (8 kernels + 1 memset)
// ---------------------------------------------------------------------------
extern "C" void kernel_launch(void* const* d_in, const int* in_sizes, int n_in,
                              void* d_out, int out_size) {
    const float* x    = (const float*)d_in[0];
    const float* xmsg = (const float*)d_in[1];
    const int*   ei   = (const int*)d_in[2];
    const int*   act  = (const int*)d_in[3];
    const float* c1w  = (const float*)d_in[4];
    const float* c1b  = (const float*)d_in[5];
    const float* c2w  = (const float*)d_in[6];
    const float* c2b  = (const float*)d_in[7];
    const float* fcw  = (const float*)d_in[8];
    const float* fcb  = (const float*)d_in[9];
    const float* muw  = (const float*)d_in[10];
    const float* mub  = (const float*)d_in[11];
    const float* msw  = (const float*)d_in[12];
    const float* msb  = (const float*)d_in[13];
    const float* g1w  = (const float*)d_in[14];
    const float* g1b  = (const float*)d_in[15];
    const float* g2w  = (const float*)d_in[16];
    const float* g2b  = (const float*)d_in[17];
    float* out = (float*)d_out;

    cudaFuncSetAttribute(k_msgout, cudaFuncAttributeMaxDynamicSharedMemorySize,
                         MS_SMEM);

    void* degp;
    cudaGetSymbolAddress(&degp, g_deg);
    cudaMemsetAsync(degp, 0, NAGENTS * sizeof(float));

    k_pre<<<547 + NEDGES / 256, 256>>>(fcw, c2w, g2w, g2b, ei);

    k_convs<<<BATCH, 256>>>(x, c1w, c1b, c2b);
    k_fc_gemm<<<512, 128>>>();
    k_lgenc<<<256 + NAGENTS / 16, 256>>>(fcb, muw, mub, act, msw, msb, xmsg,
                                         out);

    k_edge1<<<NEDGES / 256, 256>>>(ei, xmsg);
    k_g1s<<<NAGENTS * 16 / 256, 256>>>(g1w, g1b);
    k_edge2<<<NEDGES / 256, 256>>>(ei);

    k_msgout<<<NAGENTS / MS_ROWS, 256, MS_SMEM>>>(g2w, g2b, out);
}

// round 15
// speedup vs baseline: 1.1365x; 1.0021x over previous
#include <cuda_runtime.h>
#include <cuda_bf16.h>
#include <cstdint>

// ---------------------------------------------------------------------------
// Sizes (fixed by the problem)
// ---------------------------------------------------------------------------
#define BATCH    256
#define NAGENTS  8192
#define NEDGES   262144
#define ACT      21

#define L2E 1.4426950408889634f
#define LN2 0.6931471805599453f

// ---------------------------------------------------------------------------
// Scratch (device globals: no allocation allowed)
// ---------------------------------------------------------------------------
__device__ __align__(16) float g_h2t[1024 * BATCH];   // conv2 out, TRANSPOSED [k][m]
__device__ __align__(16) float g_wt[1024 * 512];      // fc_w transposed [k][n]
__device__ __align__(16) float g_w2tp[288 * 65];      // conv2 w, padded transpose [j][oc]
__device__ __align__(16) float g_part[16 * BATCH * 512]; // split-K partials
__device__ float  g_enc[NAGENTS];             // actor_encoding[0]
__device__ float  g_deg[NAGENTS];             // edge-count (no self loop)
__device__ float  g_dinv[NAGENTS];
__device__ __align__(16) float2 g_AB[NAGENTS];  // rank-2 gcn1 aggregates (final)
__device__ __align__(16) float  g_s[NAGENTS * 16]; // gcn2 edge aggregates (no self)
__device__ float  g_w2sum[16];
__device__ float  g_b2mean;

// ---------------------------------------------------------------------------
// helpers
// ---------------------------------------------------------------------------
__device__ __forceinline__ unsigned long long fma2(unsigned long long a,
                                                   unsigned long long b,
                                                   unsigned long long c) {
    unsigned long long d;
    asm("fma.rn.f32x2 %0, %1, %2, %3;" : "=l"(d) : "l"(a), "l"(b), "l"(c));
    return d;
}
__device__ __forceinline__ unsigned long long dup2(float v) {
    unsigned u = __float_as_uint(v);
    return ((unsigned long long)u << 32) | (unsigned long long)u;
}
__device__ __forceinline__ unsigned long long pack2(float lo, float hi) {
    return ((unsigned long long)__float_as_uint(hi) << 32) |
           (unsigned long long)__float_as_uint(lo);
}
__device__ __forceinline__ float flo(unsigned long long v) {
    return __uint_as_float((unsigned)v);
}
__device__ __forceinline__ float fhi(unsigned long long v) {
    return __uint_as_float((unsigned)(v >> 32));
}
__device__ __forceinline__ float ex2(float v) {
    float r;
    asm("ex2.approx.ftz.f32 %0, %1;" : "=f"(r) : "f"(v));
    return r;
}
__device__ __forceinline__ void red4(float* p, float a, float b, float c,
                                     float d) {
    asm volatile("red.global.add.v4.f32 [%0], {%1, %2, %3, %4};"
                 :: "l"(p), "f"(a), "f"(b), "f"(c), "f"(d) : "memory");
}
__device__ __forceinline__ void red2(float* p, float a, float b) {
    asm volatile("red.global.add.v2.f32 [%0], {%1, %2};"
                 :: "l"(p), "f"(a), "f"(b) : "memory");
}

// ---------------------------------------------------------------------------
// k_pre: all independent preprocessing in ONE kernel.
//  blocks [0,512)     : transpose fc_w [512][1024] -> g_wt [1024][512]
//  blocks [512,530)   : pad-transpose c2w [64][288] -> g_w2tp [288][65]
//  blocks [530,547)   : colsum(W2) (16) + mean(b2) (1)
//  blocks [547,1571)  : degree atomics (g_deg pre-zeroed by memset;
//                       self-loop +1 folded into rsqrt at consumption)
// ---------------------------------------------------------------------------
__global__ void __launch_bounds__(256) k_pre(const float* __restrict__ fc_w,
                                             const float* __restrict__ c2w,
                                             const float* __restrict__ W2,
                                             const float* __restrict__ b2,
                                             const int* __restrict__ ei) {
    const int bid = blockIdx.x, tid = threadIdx.x;
    if (bid < 512) {
        __shared__ float t[32][33];
        const int bk = bid & 31;   // 32 k-tiles
        const int bn = bid >> 5;   // 16 n-tiles
        const int tx = tid & 31, ty = tid >> 5;  // 32 x 8
#pragma unroll
        for (int i = 0; i < 32; i += 8)
            t[ty + i][tx] = fc_w[(bn * 32 + ty + i) * 1024 + bk * 32 + tx];
        __syncthreads();
#pragma unroll
        for (int i = 0; i < 32; i += 8)
            g_wt[(bk * 32 + ty + i) * 512 + bn * 32 + tx] = t[tx][ty + i];
    } else if (bid < 530) {
        int base = (bid - 512) * 1024;
#pragma unroll
        for (int q = 0; q < 4; q++) {
            int idx = base + q * 256 + tid;
            if (idx < 64 * 288) {
                int oc = idx / 288, j = idx - oc * 288;
                g_w2tp[j * 65 + oc] = c2w[idx];
            }
        }
    } else if (bid < 547) {
        int k = bid - 530;
        __shared__ float red[256];
        const float* src = (k < 16) ? (W2 + k * NAGENTS) : b2;
        float acc = 0.0f;
        for (int j = tid; j < NAGENTS; j += 256) acc += src[j];
        red[tid] = acc;
        __syncthreads();
        for (int s = 128; s; s >>= 1) {
            if (tid < s) red[tid] += red[tid + s];
            __syncthreads();
        }
        if (tid == 0) {
            if (k < 16) g_w2sum[k] = red[0];
            else        g_b2mean  = red[0] * (1.0f / (float)NAGENTS);
        }
    } else {
        int e = (bid - 547) * 256 + tid;
        if (e < NEDGES) atomicAdd(&g_deg[ei[2 * e + 1]], 1.0f);
    }
}

// ---------------------------------------------------------------------------
// Fused conv1+conv2 per batch element. One CTA per batch.
// conv2 weights staged via pure coalesced float4 copy from the pre-padded
// g_w2tp ([j][65] layout -> conflict-free quad-broadcast reads).
// Writes h2 TRANSPOSED directly (g_h2t[k][m]) for the GEMM.
// ---------------------------------------------------------------------------
__global__ void __launch_bounds__(256) k_convs(const float* __restrict__ x,
                                               const float* __restrict__ c1w,
                                               const float* __restrict__ c1b,
                                               const float* __restrict__ c2b) {
    __shared__ float xs[848];
    __shared__ float h1s[1152];
    __shared__ __align__(16) float w2s[288 * 65];
    const int b = blockIdx.x, tid = threadIdx.x;

    // stage: pure float4 copies, no div/mod, coalesced
    {
        const float4* src = (const float4*)g_w2tp;
        float4* dst = (float4*)w2s;
        for (int i = tid; i < (288 * 65) / 4; i += 256) dst[i] = src[i];
    }
    for (int i = tid; i < 845; i += 256) xs[i] = x[b * 845 + i];
    __syncthreads();

    // conv1: 1152 outputs, 4-5 per thread
    for (int idx = tid; idx < 1152; idx += 256) {
        int oc = idx / 36, p = idx % 36;
        int oy = p / 6, ox = p % 6;
        const float* wb = c1w + oc * 45;
        float acc = c1b[oc];
#pragma unroll
        for (int ic = 0; ic < 5; ic++)
#pragma unroll
            for (int ky = 0; ky < 3; ky++)
#pragma unroll
                for (int kx = 0; kx < 3; kx++)
                    acc += xs[ic * 169 + (2 * oy + ky) * 13 + 2 * ox + kx] *
                           wb[ic * 9 + ky * 3 + kx];
        h1s[idx] = fmaxf(acc, 0.0f);
    }
    __syncthreads();

    // conv2: thread -> (oc = tid/4, oy = tid%4), 4 outputs along ox
    const int oc = tid >> 2, oy = tid & 3;
    float bias = c2b[oc];
    float acc[4];
#pragma unroll
    for (int q = 0; q < 4; q++) acc[q] = bias;

#pragma unroll 4
    for (int ic = 0; ic < 32; ic++) {
#pragma unroll
        for (int ky = 0; ky < 3; ky++) {
            const float* row = &h1s[ic * 36 + (oy + ky) * 6];
            float r0 = row[0], r1 = row[1], r2 = row[2];
            float r3 = row[3], r4 = row[4], r5 = row[5];
            const float* wr = &w2s[(ic * 9 + ky * 3) * 65 + oc];
            float w0 = wr[0], w1 = wr[65], w2 = wr[130];
            acc[0] += r0 * w0 + r1 * w1 + r2 * w2;
            acc[1] += r1 * w0 + r2 * w1 + r3 * w2;
            acc[2] += r2 * w0 + r3 * w1 + r4 * w2;
            acc[3] += r3 * w0 + r4 * w1 + r5 * w2;
        }
    }
    int f0 = oc * 16 + oy * 4;
#pragma unroll
    for (int q = 0; q < 4; q++)
        g_h2t[(f0 + q) * BATCH + b] = fmaxf(acc[q], 0.0f);
}

// ---------------------------------------------------------------------------
// fc GEMM: part[ks] += h2t[kslice]^T x wt[kslice].  C = [256 x 512].
// BM=BN=64, split-K=16 (K=64 per CTA, single chunk) -> 512 CTAs
// (~3.5 CTAs/SM), 128 threads, 8x4 microtile, f32x2.
// ---------------------------------------------------------------------------
__global__ void __launch_bounds__(128) k_fc_gemm() {
    __shared__ float As[64 * 64];   // [k][m]
    __shared__ float Bs[64 * 64];   // [k][n]
    const int bx = blockIdx.x;
    const int ks = bx >> 5;           // 0..15
    const int mt = (bx >> 3) & 3;
    const int nt = bx & 7;
    const int m0 = mt * 64, n0 = nt * 64;
    const int t  = threadIdx.x;
    const int tc = t & 15, tr = t >> 4;   // tc: 4-col group, tr: 8-row group
    const int k0 = ks * 64;

    unsigned long long acc[4][4];
#pragma unroll
    for (int p = 0; p < 4; p++)
#pragma unroll
        for (int j = 0; j < 4; j++) acc[p][j] = 0ull;

    const float4* A4g = (const float4*)g_h2t;
    const float4* B4g = (const float4*)g_wt;
    float4* As4w = (float4*)As;
    float4* Bs4w = (float4*)Bs;

#pragma unroll
    for (int j = 0; j < 8; j++) {
        int idx = t + 128 * j;           // 0..1023
        int kk = idx >> 4, q = idx & 15;
        As4w[kk * 16 + q] = A4g[((k0 + kk) * BATCH + m0) / 4 + q];
        Bs4w[kk * 16 + q] = B4g[((k0 + kk) * 512 + n0) / 4 + q];
    }
    __syncthreads();

    const float4* As4 = (const float4*)As;
    const float4* Bs4 = (const float4*)Bs;
#pragma unroll 8
    for (int k = 0; k < 64; k++) {
        float4 a0 = As4[k * 16 + tr * 2];
        float4 a1 = As4[k * 16 + tr * 2 + 1];
        float4 bv = Bs4[k * 16 + tc];
        unsigned long long ap[4] = {pack2(a0.x, a0.y), pack2(a0.z, a0.w),
                                    pack2(a1.x, a1.y), pack2(a1.z, a1.w)};
        unsigned long long bd[4] = {dup2(bv.x), dup2(bv.y),
                                    dup2(bv.z), dup2(bv.w)};
#pragma unroll
        for (int p = 0; p < 4; p++)
#pragma unroll
            for (int j = 0; j < 4; j++)
                acc[p][j] = fma2(ap[p], bd[j], acc[p][j]);
    }

    float* outp = g_part + ks * (BATCH * 512);
#pragma unroll
    for (int p = 0; p < 4; p++) {
        int rlo = m0 + tr * 8 + 2 * p;
        float4 vlo = make_float4(flo(acc[p][0]), flo(acc[p][1]),
                                 flo(acc[p][2]), flo(acc[p][3]));
        float4 vhi = make_float4(fhi(acc[p][0]), fhi(acc[p][1]),
                                 fhi(acc[p][2]), fhi(acc[p][3]));
        *(float4*)(outp + rlo * 512 + n0 + tc * 4) = vlo;
        *(float4*)(outp + (rlo + 1) * 512 + n0 + tc * 4) = vhi;
    }
}

// ---------------------------------------------------------------------------
// Reconstruct one hidden row from the 16 split-K slabs + bias + relu into smem.
// ---------------------------------------------------------------------------
__device__ __forceinline__ void load_hidden_row(float* hs, int row,
                                                const float* __restrict__ fcb,
                                                int tid) {
    float2 acc = make_float2(0.0f, 0.0f);
#pragma unroll
    for (int s = 0; s < 16; s++) {
        float2 v = ((const float2*)(g_part + s * (BATCH * 512) + row * 512))[tid];
        acc.x += v.x;
        acc.y += v.y;
    }
    float2 bias = ((const float2*)fcb)[tid];
    ((float2*)hs)[tid] = make_float2(fmaxf(acc.x + bias.x, 0.0f),
                                     fmaxf(acc.y + bias.y, 0.0f));
}

// ---------------------------------------------------------------------------
// k_lgenc: fused logits head + actor-encoding + gcn node prep.
//  blocks [0,256):   logits/log_prob/entropy/action for batch row bid
//  blocks [256,512): enc[j] (32 j per block, 4 per warp -> MLP=16)
//                    + dinv[j] + self-loop AB[j]
// Output layout: [action(256) | msg_out(8192) | log_prob(256) | entropy(256)]
// ---------------------------------------------------------------------------
__global__ void __launch_bounds__(256) k_lgenc(const float* __restrict__ fcb,
                                               const float* __restrict__ muw,
                                               const float* __restrict__ mub,
                                               const int* __restrict__ action,
                                               const float* __restrict__ msw,
                                               const float* __restrict__ msb,
                                               const float* __restrict__ xm,
                                               float* __restrict__ out) {
    __shared__ float hs[512];
    __shared__ float lg[24];
    const int bid = blockIdx.x, tid = threadIdx.x;
    const int wid = tid >> 5, lane = tid & 31;

    if (bid < 256) {
        load_hidden_row(hs, bid, fcb, tid);
        __syncthreads();

        const float4* h4 = (const float4*)hs;
        for (int a = wid; a < ACT; a += 8) {
            const float4* wr = (const float4*)(muw + a * 512);
            float acc = 0.0f;
#pragma unroll
            for (int i = 0; i < 4; i++) {
                float4 w = wr[lane + i * 32];
                float4 h = h4[lane + i * 32];
                acc += w.x * h.x + w.y * h.y + w.z * h.z + w.w * h.w;
            }
#pragma unroll
            for (int o = 16; o; o >>= 1)
                acc += __shfl_xor_sync(0xffffffffu, acc, o);
            if (lane == 0) lg[a] = acc + mub[a];
        }
        __syncthreads();

        if (wid == 0) {
            float l = (lane < ACT) ? lg[lane] : -3.4e38f;
            float m = l;
#pragma unroll
            for (int o = 16; o; o >>= 1)
                m = fmaxf(m, __shfl_xor_sync(0xffffffffu, m, o));
            float e  = (lane < ACT) ? __expf(l - m) : 0.0f;
            float el = (lane < ACT) ? e * l : 0.0f;
            float se = e, sel = el;
#pragma unroll
            for (int o = 16; o; o >>= 1) {
                se  += __shfl_xor_sync(0xffffffffu, se, o);
                sel += __shfl_xor_sync(0xffffffffu, sel, o);
            }
            int a = action[bid];
            float la = __shfl_sync(0xffffffffu, l, a);
            if (lane == 0) {
                float lse = m + __logf(se);
                out[BATCH + NAGENTS + bid]     = la - lse;        // log_prob
                out[2 * BATCH + NAGENTS + bid] = lse - sel / se;  // entropy
                out[bid] = (float)a;                              // action
            }
        }
    } else {
        load_hidden_row(hs, 0, fcb, tid);
        __syncthreads();

        // four agents per warp: 16 independent LDG.128 in flight per thread
        const int j0 = (bid - 256) * 32 + wid * 4;
        const float4* h4 = (const float4*)hs;
        float acc[4] = {0.0f, 0.0f, 0.0f, 0.0f};
#pragma unroll
        for (int i = 0; i < 4; i++) {
            float4 h = h4[lane + i * 32];
#pragma unroll
            for (int q = 0; q < 4; q++) {
                float4 w = ((const float4*)(msw + (j0 + q) * 512))[lane + i * 32];
                acc[q] += w.x * h.x + w.y * h.y + w.z * h.z + w.w * h.w;
            }
        }
#pragma unroll
        for (int o = 16; o; o >>= 1)
#pragma unroll
            for (int q = 0; q < 4; q++)
                acc[q] += __shfl_xor_sync(0xffffffffu, acc[q], o);
        if (lane == 0) {
#pragma unroll
            for (int q = 0; q < 4; q++) {
                int j = j0 + q;
                float e = acc[q] + msb[j];
                g_enc[j] = e;
                float dv = rsqrtf(g_deg[j] + 1.0f);   // +1 = self loop
                g_dinv[j] = dv;
                float d2 = dv * dv;                   // self-loop norm
                g_AB[j] = make_float2(d2 * xm[j], d2 * e);
            }
        }
    }
}

// ---------------------------------------------------------------------------
// GCN edge aggregation. g1 is rank-2 -> recomputed on the fly from AB (8-byte
// gather) instead of materializing/gathering a 64-byte g1 row per edge.
// ---------------------------------------------------------------------------
__global__ void k_edge1(const int* __restrict__ ei,
                        const float* __restrict__ xm) {
    int e = blockIdx.x * 256 + threadIdx.x;
    if (e >= NEDGES) return;
    int s = ei[2 * e], d = ei[2 * e + 1];
    float nrm = g_dinv[s] * g_dinv[d];
    red2((float*)&g_AB[d], nrm * xm[s], nrm * g_enc[s]);
}

__global__ void __launch_bounds__(256) k_edge2(const int* __restrict__ ei,
                                               const float* __restrict__ w1,
                                               const float* __restrict__ b1) {
    __shared__ float w1s[48];
    const int tid = threadIdx.x;
    if (tid < 48) w1s[tid] = (tid < 32) ? w1[tid] : b1[tid - 32];
    __syncthreads();

    int e = blockIdx.x * 256 + tid;
    if (e >= NEDGES) return;
    int s = ei[2 * e], d = ei[2 * e + 1];
    float nrm = g_dinv[s] * g_dinv[d];
    float2 ab = g_AB[s];
    float* sd = g_s + d * 16;
#pragma unroll
    for (int q = 0; q < 4; q++) {
        float v0 = fmaxf(ab.x * w1s[q*4+0] + ab.y * w1s[16+q*4+0] + w1s[32+q*4+0], 0.0f);
        float v1 = fmaxf(ab.x * w1s[q*4+1] + ab.y * w1s[16+q*4+1] + w1s[32+q*4+1], 0.0f);
        float v2 = fmaxf(ab.x * w1s[q*4+2] + ab.y * w1s[16+q*4+2] + w1s[32+q*4+2], 0.0f);
        float v3 = fmaxf(ab.x * w1s[q*4+3] + ab.y * w1s[16+q*4+3] + w1s[32+q*4+3], 0.0f);
        red4(sd + q * 4, nrm * v0, nrm * v1, nrm * v2, nrm * v3);
    }
}

// ---------------------------------------------------------------------------
// K12: msg_out[i] = mean_j(g_ij) - lse_j(g_ij) with g_ij = s[i].W2[:,j]+b2[j].
// s[i][k] = g_s[i][k] (edge REDs) + dinv[i]^2 * relu(AB[i].W1[:,k]+b1[k])
// (self-loop term folded in here; g_s zeroed by memset, no init kernel).
// 16 rows/CTA, W2 streamed in 16x1024 SMEM chunks, f32x2 FMA, log2-domain
// accumulation -> raw ex2, no max tracking (|g| analytically bounded).
// ---------------------------------------------------------------------------
#define MS_CHUNK 1024
#define MS_ROWS  16
#define MS_SMEM  (16 * MS_CHUNK * 4 + MS_ROWS * 16 * 8 + MS_ROWS * 16 * 4)

__global__ void __launch_bounds__(256) k_msgout(const float* __restrict__ W2,
                                                const float* __restrict__ b2,
                                                const float* __restrict__ w1,
                                                const float* __restrict__ b1,
                                                float* __restrict__ out) {
    extern __shared__ char smraw[];
    float* wsm = (float*)smraw;                                    // 16*1024 f
    unsigned long long* sdup =
        (unsigned long long*)(smraw + 16 * MS_CHUNK * 4);          // 256 u64
    float* slin = (float*)(smraw + 16 * MS_CHUNK * 4 + 256 * 8);   // 256 f

    const int tid  = threadIdx.x;
    const int row0 = blockIdx.x * MS_ROWS;

    {   // s_final = edge aggregate + self-loop term (g1 recomputed from AB)
        int r = tid >> 4, k = tid & 15;
        int row = row0 + r;
        float dv = g_dinv[row];
        float2 ab = g_AB[row];
        float v = fmaxf(ab.x * w1[k] + ab.y * w1[16 + k] + b1[k], 0.0f);
        float sfin = g_s[row * 16 + k] + dv * dv * v;
        slin[tid] = sfin;
        sdup[tid] = dup2(sfin * L2E);
    }

    float sr[MS_ROWS];
#pragma unroll
    for (int r = 0; r < MS_ROWS; r++) sr[r] = 0.0f;

    const float4* gw4 = (const float4*)W2;

    for (int chunk = 0; chunk < NAGENTS / MS_CHUNK; chunk++) {
        int base = chunk * MS_CHUNK;
        __syncthreads();
#pragma unroll
        for (int k = 0; k < 16; k++)
            ((float4*)wsm)[k * 256 + tid] = gw4[(k * NAGENTS + base) / 4 + tid];
        float4 bb = ((const float4*)(b2 + base))[tid];
        __syncthreads();

        unsigned long long acc0[MS_ROWS], acc1[MS_ROWS];
        unsigned long long b01 = pack2(bb.x * L2E, bb.y * L2E);
        unsigned long long b23 = pack2(bb.z * L2E, bb.w * L2E);
#pragma unroll
        for (int r = 0; r < MS_ROWS; r++) { acc0[r] = b01; acc1[r] = b23; }

        const ulonglong2* wU2 = (const ulonglong2*)wsm;
#pragma unroll
        for (int k = 0; k < 16; k++) {
            ulonglong2 w = wU2[k * 256 + tid];    // LDS.128, conflict-free
#pragma unroll
            for (int r = 0; r < MS_ROWS; r++) {
                unsigned long long sv = sdup[r * 16 + k];  // broadcast
                acc0[r] = fma2(w.x, sv, acc0[r]);
                acc1[r] = fma2(w.y, sv, acc1[r]);
            }
        }
#pragma unroll
        for (int r = 0; r < MS_ROWS; r++) {
            sr[r] += ex2(flo(acc0[r])) + ex2(fhi(acc0[r])) +
                     ex2(flo(acc1[r])) + ex2(fhi(acc1[r]));
        }
    }

    // block sum-reduce per row; alias onto wsm (16KB)
    __syncthreads();
    float* rs = wsm;              // [16][256]
#pragma unroll
    for (int r = 0; r < MS_ROWS; r++) rs[r * 256 + tid] = sr[r];
    for (int step = 128; step > 0; step >>= 1) {
        __syncthreads();
        if (tid < step) {
#pragma unroll
            for (int r = 0; r < MS_ROWS; r++)
                rs[r * 256 + tid] += rs[r * 256 + tid + step];
        }
    }
    __syncthreads();
    if (tid < MS_ROWS) {
        int row = row0 + tid;
        float lse = LN2 * __log2f(rs[tid * 256]);
        float acc = 0.0f;
#pragma unroll
        for (int k = 0; k < 16; k++) acc += slin[tid * 16 + k] * g_w2sum[k];
        out[BATCH + row] = acc * (1.0f / (float)NAGENTS) + g_b2mean - lse;
    }
}

// ---------------------------------------------------------------------------
// launch (7 kernels + 2 memsets)
// ---------------------------------------------------------------------------
extern "C" void kernel_launch(void* const* d_in, const int* in_sizes, int n_in,
                              void* d_out, int out_size) {
    const float* x    = (const float*)d_in[0];
    const float* xmsg = (const float*)d_in[1];
    const int*   ei   = (const int*)d_in[2];
    const int*   act  = (const int*)d_in[3];
    const float* c1w  = (const float*)d_in[4];
    const float* c1b  = (const float*)d_in[5];
    const float* c2w  = (const float*)d_in[6];
    const float* c2b  = (const float*)d_in[7];
    const float* fcw  = (const float*)d_in[8];
    const float* fcb  = (const float*)d_in[9];
    const float* muw  = (const float*)d_in[10];
    const float* mub  = (const float*)d_in[11];
    const float* msw  = (const float*)d_in[12];
    const float* msb  = (const float*)d_in[13];
    const float* g1w  = (const float*)d_in[14];
    const float* g1b  = (const float*)d_in[15];
    const float* g2w  = (const float*)d_in[16];
    const float* g2b  = (const float*)d_in[17];
    float* out = (float*)d_out;

    cudaFuncSetAttribute(k_msgout, cudaFuncAttributeMaxDynamicSharedMemorySize,
                         MS_SMEM);

    void* degp;
    cudaGetSymbolAddress(&degp, g_deg);
    cudaMemsetAsync(degp, 0, NAGENTS * sizeof(float));
    void* sp;
    cudaGetSymbolAddress(&sp, g_s);
    cudaMemsetAsync(sp, 0, NAGENTS * 16 * sizeof(float));

    k_pre<<<547 + NEDGES / 256, 256>>>(fcw, c2w, g2w, g2b, ei);

    k_convs<<<BATCH, 256>>>(x, c1w, c1b, c2b);
    k_fc_gemm<<<512, 128>>>();
    k_lgenc<<<512, 256>>>(fcb, muw, mub, act, msw, msb, xmsg, out);

    k_edge1<<<NEDGES / 256, 256>>>(ei, xmsg);
    k_edge2<<<NEDGES / 256, 256>>>(ei, g1w, g1b);

    k_msgout<<<NAGENTS / MS_ROWS, 256, MS_SMEM>>>(g2w, g2b, g1w, g1b, out);
}

// round 16
// speedup vs baseline: 1.1914x; 1.0483x over previous
#include <cuda_runtime.h>
#include <cuda_bf16.h>
#include <cstdint>

// ---------------------------------------------------------------------------
// Sizes (fixed by the problem)
// ---------------------------------------------------------------------------
#define BATCH    256
#define NAGENTS  8192
#define NEDGES   262144
#define ACT      21

#define L2E 1.4426950408889634f
#define LN2 0.6931471805599453f

// ---------------------------------------------------------------------------
// Scratch (device globals: no allocation allowed)
// One contiguous zero-initialized region (single memset):
//   [0, N)              g_deg
//   [N, N+16N)          g_s
//   [N+16N, +BATCH*512) g_hidden (raw GEMM accumulator, bias/relu at read)
// ---------------------------------------------------------------------------
#define ZB_DEG    0
#define ZB_S      (NAGENTS)
#define ZB_HID    (NAGENTS + NAGENTS * 16)
#define ZB_TOTAL  (NAGENTS + NAGENTS * 16 + BATCH * 512)
__device__ __align__(16) float g_zbuf[ZB_TOTAL];
#define g_deg    (g_zbuf + ZB_DEG)
#define g_s      (g_zbuf + ZB_S)
#define g_hidden (g_zbuf + ZB_HID)

__device__ __align__(16) float g_h2t[1024 * BATCH];   // conv2 out, TRANSPOSED [k][m]
__device__ __align__(16) float g_wt[1024 * 512];      // fc_w transposed [k][n]
__device__ __align__(16) float g_w2tp[288 * 65];      // conv2 w, padded transpose [j][oc]
__device__ float  g_enc[NAGENTS];             // actor_encoding[0]
__device__ float  g_dinv[NAGENTS];
__device__ __align__(16) float2 g_AB[NAGENTS];  // rank-2 gcn1 aggregates (final)
__device__ float  g_w2sum[16];
__device__ float  g_b2mean;

// ---------------------------------------------------------------------------
// helpers
// ---------------------------------------------------------------------------
__device__ __forceinline__ unsigned long long fma2(unsigned long long a,
                                                   unsigned long long b,
                                                   unsigned long long c) {
    unsigned long long d;
    asm("fma.rn.f32x2 %0, %1, %2, %3;" : "=l"(d) : "l"(a), "l"(b), "l"(c));
    return d;
}
__device__ __forceinline__ unsigned long long dup2(float v) {
    unsigned u = __float_as_uint(v);
    return ((unsigned long long)u << 32) | (unsigned long long)u;
}
__device__ __forceinline__ unsigned long long pack2(float lo, float hi) {
    return ((unsigned long long)__float_as_uint(hi) << 32) |
           (unsigned long long)__float_as_uint(lo);
}
__device__ __forceinline__ float flo(unsigned long long v) {
    return __uint_as_float((unsigned)v);
}
__device__ __forceinline__ float fhi(unsigned long long v) {
    return __uint_as_float((unsigned)(v >> 32));
}
__device__ __forceinline__ float ex2(float v) {
    float r;
    asm("ex2.approx.ftz.f32 %0, %1;" : "=f"(r) : "f"(v));
    return r;
}
__device__ __forceinline__ void red4(float* p, float a, float b, float c,
                                     float d) {
    asm volatile("red.global.add.v4.f32 [%0], {%1, %2, %3, %4};"
                 :: "l"(p), "f"(a), "f"(b), "f"(c), "f"(d) : "memory");
}
__device__ __forceinline__ void red2(float* p, float a, float b) {
    asm volatile("red.global.add.v2.f32 [%0], {%1, %2};"
                 :: "l"(p), "f"(a), "f"(b) : "memory");
}

// ---------------------------------------------------------------------------
// k_pre: all independent preprocessing in ONE kernel.
//  blocks [0,512)     : transpose fc_w [512][1024] -> g_wt [1024][512]
//  blocks [512,530)   : pad-transpose c2w [64][288] -> g_w2tp [288][65]
//  blocks [530,547)   : colsum(W2) (16) + mean(b2) (1)
//  blocks [547,1571)  : degree atomics (g_deg pre-zeroed by memset;
//                       self-loop +1 folded into rsqrt at consumption)
// ---------------------------------------------------------------------------
__global__ void __launch_bounds__(256) k_pre(const float* __restrict__ fc_w,
                                             const float* __restrict__ c2w,
                                             const float* __restrict__ W2,
                                             const float* __restrict__ b2,
                                             const int* __restrict__ ei) {
    const int bid = blockIdx.x, tid = threadIdx.x;
    if (bid < 512) {
        __shared__ float t[32][33];
        const int bk = bid & 31;   // 32 k-tiles
        const int bn = bid >> 5;   // 16 n-tiles
        const int tx = tid & 31, ty = tid >> 5;  // 32 x 8
#pragma unroll
        for (int i = 0; i < 32; i += 8)
            t[ty + i][tx] = fc_w[(bn * 32 + ty + i) * 1024 + bk * 32 + tx];
        __syncthreads();
#pragma unroll
        for (int i = 0; i < 32; i += 8)
            g_wt[(bk * 32 + ty + i) * 512 + bn * 32 + tx] = t[tx][ty + i];
    } else if (bid < 530) {
        int base = (bid - 512) * 1024;
#pragma unroll
        for (int q = 0; q < 4; q++) {
            int idx = base + q * 256 + tid;
            if (idx < 64 * 288) {
                int oc = idx / 288, j = idx - oc * 288;
                g_w2tp[j * 65 + oc] = c2w[idx];
            }
        }
    } else if (bid < 547) {
        int k = bid - 530;
        __shared__ float red[256];
        const float* src = (k < 16) ? (W2 + k * NAGENTS) : b2;
        float acc = 0.0f;
        for (int j = tid; j < NAGENTS; j += 256) acc += src[j];
        red[tid] = acc;
        __syncthreads();
        for (int s = 128; s; s >>= 1) {
            if (tid < s) red[tid] += red[tid + s];
            __syncthreads();
        }
        if (tid == 0) {
            if (k < 16) g_w2sum[k] = red[0];
            else        g_b2mean  = red[0] * (1.0f / (float)NAGENTS);
        }
    } else {
        int e = (bid - 547) * 256 + tid;
        if (e < NEDGES) atomicAdd(&g_deg[ei[2 * e + 1]], 1.0f);
    }
}

// ---------------------------------------------------------------------------
// Fused conv1+conv2 per batch element. One CTA per batch.
// conv2 weights staged via pure coalesced float4 copy from the pre-padded
// g_w2tp ([j][65] layout -> conflict-free quad-broadcast reads).
// Writes h2 TRANSPOSED directly (g_h2t[k][m]) for the GEMM.
// ---------------------------------------------------------------------------
__global__ void __launch_bounds__(256) k_convs(const float* __restrict__ x,
                                               const float* __restrict__ c1w,
                                               const float* __restrict__ c1b,
                                               const float* __restrict__ c2b) {
    __shared__ float xs[848];
    __shared__ float h1s[1152];
    __shared__ __align__(16) float w2s[288 * 65];
    const int b = blockIdx.x, tid = threadIdx.x;

    // stage: pure float4 copies, no div/mod, coalesced
    {
        const float4* src = (const float4*)g_w2tp;
        float4* dst = (float4*)w2s;
        for (int i = tid; i < (288 * 65) / 4; i += 256) dst[i] = src[i];
    }
    for (int i = tid; i < 845; i += 256) xs[i] = x[b * 845 + i];
    __syncthreads();

    // conv1: 1152 outputs, 4-5 per thread
    for (int idx = tid; idx < 1152; idx += 256) {
        int oc = idx / 36, p = idx % 36;
        int oy = p / 6, ox = p % 6;
        const float* wb = c1w + oc * 45;
        float acc = c1b[oc];
#pragma unroll
        for (int ic = 0; ic < 5; ic++)
#pragma unroll
            for (int ky = 0; ky < 3; ky++)
#pragma unroll
                for (int kx = 0; kx < 3; kx++)
                    acc += xs[ic * 169 + (2 * oy + ky) * 13 + 2 * ox + kx] *
                           wb[ic * 9 + ky * 3 + kx];
        h1s[idx] = fmaxf(acc, 0.0f);
    }
    __syncthreads();

    // conv2: thread -> (oc = tid/4, oy = tid%4), 4 outputs along ox
    const int oc = tid >> 2, oy = tid & 3;
    float bias = c2b[oc];
    float acc[4];
#pragma unroll
    for (int q = 0; q < 4; q++) acc[q] = bias;

#pragma unroll 4
    for (int ic = 0; ic < 32; ic++) {
#pragma unroll
        for (int ky = 0; ky < 3; ky++) {
            const float* row = &h1s[ic * 36 + (oy + ky) * 6];
            float r0 = row[0], r1 = row[1], r2 = row[2];
            float r3 = row[3], r4 = row[4], r5 = row[5];
            const float* wr = &w2s[(ic * 9 + ky * 3) * 65 + oc];
            float w0 = wr[0], w1 = wr[65], w2 = wr[130];
            acc[0] += r0 * w0 + r1 * w1 + r2 * w2;
            acc[1] += r1 * w0 + r2 * w1 + r3 * w2;
            acc[2] += r2 * w0 + r3 * w1 + r4 * w2;
            acc[3] += r3 * w0 + r4 * w1 + r5 * w2;
        }
    }
    int f0 = oc * 16 + oy * 4;
#pragma unroll
    for (int q = 0; q < 4; q++)
        g_h2t[(f0 + q) * BATCH + b] = fmaxf(acc[q], 0.0f);
}

// ---------------------------------------------------------------------------
// fc GEMM: g_hidden += h2t[kslice]^T x wt[kslice] via red.global.add.v4.
// C = [256 x 512].  BM=BN=64, split-K=16 (K=64/CTA, single chunk) -> 512 CTAs,
// 128 threads, 8x4 microtile, f32x2. g_hidden is memset-zeroed; bias+relu
// applied at read time.
// ---------------------------------------------------------------------------
__global__ void __launch_bounds__(128) k_fc_gemm() {
    __shared__ float As[64 * 64];   // [k][m]
    __shared__ float Bs[64 * 64];   // [k][n]
    const int bx = blockIdx.x;
    const int ks = bx >> 5;           // 0..15
    const int mt = (bx >> 3) & 3;
    const int nt = bx & 7;
    const int m0 = mt * 64, n0 = nt * 64;
    const int t  = threadIdx.x;
    const int tc = t & 15, tr = t >> 4;   // tc: 4-col group, tr: 8-row group
    const int k0 = ks * 64;

    unsigned long long acc[4][4];
#pragma unroll
    for (int p = 0; p < 4; p++)
#pragma unroll
        for (int j = 0; j < 4; j++) acc[p][j] = 0ull;

    const float4* A4g = (const float4*)g_h2t;
    const float4* B4g = (const float4*)g_wt;
    float4* As4w = (float4*)As;
    float4* Bs4w = (float4*)Bs;

#pragma unroll
    for (int j = 0; j < 8; j++) {
        int idx = t + 128 * j;           // 0..1023
        int kk = idx >> 4, q = idx & 15;
        As4w[kk * 16 + q] = A4g[((k0 + kk) * BATCH + m0) / 4 + q];
        Bs4w[kk * 16 + q] = B4g[((k0 + kk) * 512 + n0) / 4 + q];
    }
    __syncthreads();

    const float4* As4 = (const float4*)As;
    const float4* Bs4 = (const float4*)Bs;
#pragma unroll 8
    for (int k = 0; k < 64; k++) {
        float4 a0 = As4[k * 16 + tr * 2];
        float4 a1 = As4[k * 16 + tr * 2 + 1];
        float4 bv = Bs4[k * 16 + tc];
        unsigned long long ap[4] = {pack2(a0.x, a0.y), pack2(a0.z, a0.w),
                                    pack2(a1.x, a1.y), pack2(a1.z, a1.w)};
        unsigned long long bd[4] = {dup2(bv.x), dup2(bv.y),
                                    dup2(bv.z), dup2(bv.w)};
#pragma unroll
        for (int p = 0; p < 4; p++)
#pragma unroll
            for (int j = 0; j < 4; j++)
                acc[p][j] = fma2(ap[p], bd[j], acc[p][j]);
    }

#pragma unroll
    for (int p = 0; p < 4; p++) {
        int rlo = m0 + tr * 8 + 2 * p;
        red4(g_hidden + rlo * 512 + n0 + tc * 4,
             flo(acc[p][0]), flo(acc[p][1]), flo(acc[p][2]), flo(acc[p][3]));
        red4(g_hidden + (rlo + 1) * 512 + n0 + tc * 4,
             fhi(acc[p][0]), fhi(acc[p][1]), fhi(acc[p][2]), fhi(acc[p][3]));
    }
}

// ---------------------------------------------------------------------------
// Load one hidden row (raw GEMM accumulator) + bias + relu into smem.
// ---------------------------------------------------------------------------
__device__ __forceinline__ void load_hidden_row(float* hs, int row,
                                                const float* __restrict__ fcb,
                                                int tid) {
    float2 v = ((const float2*)(g_hidden + row * 512))[tid];
    float2 bias = ((const float2*)fcb)[tid];
    ((float2*)hs)[tid] = make_float2(fmaxf(v.x + bias.x, 0.0f),
                                     fmaxf(v.y + bias.y, 0.0f));
}

// ---------------------------------------------------------------------------
// k_lgenc: fused logits head + actor-encoding + gcn node prep.
//  blocks [0,256):   logits/log_prob/entropy/action for batch row bid
//  blocks [256,512): enc[j] (32 j per block, 4 per warp -> MLP=16)
//                    + dinv[j] + self-loop AB[j]
// Output layout: [action(256) | msg_out(8192) | log_prob(256) | entropy(256)]
// ---------------------------------------------------------------------------
__global__ void __launch_bounds__(256) k_lgenc(const float* __restrict__ fcb,
                                               const float* __restrict__ muw,
                                               const float* __restrict__ mub,
                                               const int* __restrict__ action,
                                               const float* __restrict__ msw,
                                               const float* __restrict__ msb,
                                               const float* __restrict__ xm,
                                               float* __restrict__ out) {
    __shared__ float hs[512];
    __shared__ float lg[24];
    const int bid = blockIdx.x, tid = threadIdx.x;
    const int wid = tid >> 5, lane = tid & 31;

    if (bid < 256) {
        load_hidden_row(hs, bid, fcb, tid);
        __syncthreads();

        const float4* h4 = (const float4*)hs;
        for (int a = wid; a < ACT; a += 8) {
            const float4* wr = (const float4*)(muw + a * 512);
            float acc = 0.0f;
#pragma unroll
            for (int i = 0; i < 4; i++) {
                float4 w = wr[lane + i * 32];
                float4 h = h4[lane + i * 32];
                acc += w.x * h.x + w.y * h.y + w.z * h.z + w.w * h.w;
            }
#pragma unroll
            for (int o = 16; o; o >>= 1)
                acc += __shfl_xor_sync(0xffffffffu, acc, o);
            if (lane == 0) lg[a] = acc + mub[a];
        }
        __syncthreads();

        if (wid == 0) {
            float l = (lane < ACT) ? lg[lane] : -3.4e38f;
            float m = l;
#pragma unroll
            for (int o = 16; o; o >>= 1)
                m = fmaxf(m, __shfl_xor_sync(0xffffffffu, m, o));
            float e  = (lane < ACT) ? __expf(l - m) : 0.0f;
            float el = (lane < ACT) ? e * l : 0.0f;
            float se = e, sel = el;
#pragma unroll
            for (int o = 16; o; o >>= 1) {
                se  += __shfl_xor_sync(0xffffffffu, se, o);
                sel += __shfl_xor_sync(0xffffffffu, sel, o);
            }
            int a = action[bid];
            float la = __shfl_sync(0xffffffffu, l, a);
            if (lane == 0) {
                float lse = m + __logf(se);
                out[BATCH + NAGENTS + bid]     = la - lse;        // log_prob
                out[2 * BATCH + NAGENTS + bid] = lse - sel / se;  // entropy
                out[bid] = (float)a;                              // action
            }
        }
    } else {
        load_hidden_row(hs, 0, fcb, tid);
        __syncthreads();

        // four agents per warp: 16 independent LDG.128 in flight per thread
        const int j0 = (bid - 256) * 32 + wid * 4;
        const float4* h4 = (const float4*)hs;
        float acc[4] = {0.0f, 0.0f, 0.0f, 0.0f};
#pragma unroll
        for (int i = 0; i < 4; i++) {
            float4 h = h4[lane + i * 32];
#pragma unroll
            for (int q = 0; q < 4; q++) {
                float4 w = ((const float4*)(msw + (j0 + q) * 512))[lane + i * 32];
                acc[q] += w.x * h.x + w.y * h.y + w.z * h.z + w.w * h.w;
            }
        }
#pragma unroll
        for (int o = 16; o; o >>= 1)
#pragma unroll
            for (int q = 0; q < 4; q++)
                acc[q] += __shfl_xor_sync(0xffffffffu, acc[q], o);
        if (lane == 0) {
#pragma unroll
            for (int q = 0; q < 4; q++) {
                int j = j0 + q;
                float e = acc[q] + msb[j];
                g_enc[j] = e;
                float dv = rsqrtf(g_deg[j] + 1.0f);   // +1 = self loop
                g_dinv[j] = dv;
                float d2 = dv * dv;                   // self-loop norm
                g_AB[j] = make_float2(d2 * xm[j], d2 * e);
            }
        }
    }
}

// ---------------------------------------------------------------------------
// GCN edge aggregation. g1 is rank-2 -> recomputed on the fly from AB (8-byte
// gather) instead of materializing/gathering a 64-byte g1 row per edge.
// ---------------------------------------------------------------------------
__global__ void k_edge1(const int* __restrict__ ei,
                        const float* __restrict__ xm) {
    int e = blockIdx.x * 256 + threadIdx.x;
    if (e >= NEDGES) return;
    int s = ei[2 * e], d = ei[2 * e + 1];
    float nrm = g_dinv[s] * g_dinv[d];
    red2((float*)&g_AB[d], nrm * xm[s], nrm * g_enc[s]);
}

__global__ void __launch_bounds__(256) k_edge2(const int* __restrict__ ei,
                                               const float* __restrict__ w1,
                                               const float* __restrict__ b1) {
    __shared__ float w1s[48];
    const int tid = threadIdx.x;
    if (tid < 48) w1s[tid] = (tid < 32) ? w1[tid] : b1[tid - 32];
    __syncthreads();

    int e = blockIdx.x * 256 + tid;
    if (e >= NEDGES) return;
    int s = ei[2 * e], d = ei[2 * e + 1];
    float nrm = g_dinv[s] * g_dinv[d];
    float2 ab = g_AB[s];
    float* sd = g_s + d * 16;
#pragma unroll
    for (int q = 0; q < 4; q++) {
        float v0 = fmaxf(ab.x * w1s[q*4+0] + ab.y * w1s[16+q*4+0] + w1s[32+q*4+0], 0.0f);
        float v1 = fmaxf(ab.x * w1s[q*4+1] + ab.y * w1s[16+q*4+1] + w1s[32+q*4+1], 0.0f);
        float v2 = fmaxf(ab.x * w1s[q*4+2] + ab.y * w1s[16+q*4+2] + w1s[32+q*4+2], 0.0f);
        float v3 = fmaxf(ab.x * w1s[q*4+3] + ab.y * w1s[16+q*4+3] + w1s[32+q*4+3], 0.0f);
        red4(sd + q * 4, nrm * v0, nrm * v1, nrm * v2, nrm * v3);
    }
}

// ---------------------------------------------------------------------------
// K12: msg_out[i] = mean_j(g_ij) - lse_j(g_ij) with g_ij = s[i].W2[:,j]+b2[j].
// s[i][k] = g_s[i][k] (edge REDs) + dinv[i]^2 * relu(AB[i].W1[:,k]+b1[k]).
// 16 rows/CTA, W2 streamed in 16x1024 SMEM chunks, f32x2 FMA, log2-domain
// accumulation -> raw ex2. k processed in PAIRS with ulonglong2 sdup loads
// (halves broadcast-LDS issue count in the hot loop).
// ---------------------------------------------------------------------------
#define MS_CHUNK 1024
#define MS_ROWS  16
#define MS_SMEM  (16 * MS_CHUNK * 4 + MS_ROWS * 16 * 8 + MS_ROWS * 16 * 4)

__global__ void __launch_bounds__(256) k_msgout(const float* __restrict__ W2,
                                                const float* __restrict__ b2,
                                                const float* __restrict__ w1,
                                                const float* __restrict__ b1,
                                                float* __restrict__ out) {
    extern __shared__ char smraw[];
    float* wsm = (float*)smraw;                                    // 16*1024 f
    unsigned long long* sdup =
        (unsigned long long*)(smraw + 16 * MS_CHUNK * 4);          // 256 u64
    float* slin = (float*)(smraw + 16 * MS_CHUNK * 4 + 256 * 8);   // 256 f

    const int tid  = threadIdx.x;
    const int row0 = blockIdx.x * MS_ROWS;

    {   // s_final = edge aggregate + self-loop term (g1 recomputed from AB)
        int r = tid >> 4, k = tid & 15;
        int row = row0 + r;
        float dv = g_dinv[row];
        float2 ab = g_AB[row];
        float v = fmaxf(ab.x * w1[k] + ab.y * w1[16 + k] + b1[k], 0.0f);
        float sfin = g_s[row * 16 + k] + dv * dv * v;
        slin[tid] = sfin;
        sdup[tid] = dup2(sfin * L2E);
    }

    float sr[MS_ROWS];
#pragma unroll
    for (int r = 0; r < MS_ROWS; r++) sr[r] = 0.0f;

    const float4* gw4 = (const float4*)W2;

    for (int chunk = 0; chunk < NAGENTS / MS_CHUNK; chunk++) {
        int base = chunk * MS_CHUNK;
        __syncthreads();
#pragma unroll
        for (int k = 0; k < 16; k++)
            ((float4*)wsm)[k * 256 + tid] = gw4[(k * NAGENTS + base) / 4 + tid];
        float4 bb = ((const float4*)(b2 + base))[tid];
        __syncthreads();

        unsigned long long acc0[MS_ROWS], acc1[MS_ROWS];
        unsigned long long b01 = pack2(bb.x * L2E, bb.y * L2E);
        unsigned long long b23 = pack2(bb.z * L2E, bb.w * L2E);
#pragma unroll
        for (int r = 0; r < MS_ROWS; r++) { acc0[r] = b01; acc1[r] = b23; }

        const ulonglong2* wU2 = (const ulonglong2*)wsm;
        const ulonglong2* sd2 = (const ulonglong2*)sdup;  // pairs (k, k+1)
#pragma unroll
        for (int kp = 0; kp < 8; kp++) {
            ulonglong2 wa = wU2[(2 * kp) * 256 + tid];      // k = 2kp
            ulonglong2 wb = wU2[(2 * kp + 1) * 256 + tid];  // k = 2kp+1
#pragma unroll
            for (int r = 0; r < MS_ROWS; r++) {
                ulonglong2 sv = sd2[r * 8 + kp];   // broadcast LDS.128
                acc0[r] = fma2(wa.x, sv.x, acc0[r]);
                acc1[r] = fma2(wa.y, sv.x, acc1[r]);
                acc0[r] = fma2(wb.x, sv.y, acc0[r]);
                acc1[r] = fma2(wb.y, sv.y, acc1[r]);
            }
        }
#pragma unroll
        for (int r = 0; r < MS_ROWS; r++) {
            sr[r] += ex2(flo(acc0[r])) + ex2(fhi(acc0[r])) +
                     ex2(flo(acc1[r])) + ex2(fhi(acc1[r]));
        }
    }

    // block sum-reduce per row; alias onto wsm (16KB)
    __syncthreads();
    float* rs = wsm;              // [16][256]
#pragma unroll
    for (int r = 0; r < MS_ROWS; r++) rs[r * 256 + tid] = sr[r];
    for (int step = 128; step > 0; step >>= 1) {
        __syncthreads();
        if (tid < step) {
#pragma unroll
            for (int r = 0; r < MS_ROWS; r++)
                rs[r * 256 + tid] += rs[r * 256 + tid + step];
        }
    }
    __syncthreads();
    if (tid < MS_ROWS) {
        int row = row0 + tid;
        float lse = LN2 * __log2f(rs[tid * 256]);
        float acc = 0.0f;
#pragma unroll
        for (int k = 0; k < 16; k++) acc += slin[tid * 16 + k] * g_w2sum[k];
        out[BATCH + row] = acc * (1.0f / (float)NAGENTS) + g_b2mean - lse;
    }
}

// ---------------------------------------------------------------------------
// launch (7 kernels + 1 memset)
// ---------------------------------------------------------------------------
extern "C" void kernel_launch(void* const* d_in, const int* in_sizes, int n_in,
                              void* d_out, int out_size) {
    const float* x    = (const float*)d_in[0];
    const float* xmsg = (const float*)d_in[1];
    const int*   ei   = (const int*)d_in[2];
    const int*   act  = (const int*)d_in[3];
    const float* c1w  = (const float*)d_in[4];
    const float* c1b  = (const float*)d_in[5];
    const float* c2w  = (const float*)d_in[6];
    const float* c2b  = (const float*)d_in[7];
    const float* fcw  = (const float*)d_in[8];
    const float* fcb  = (const float*)d_in[9];
    const float* muw  = (const float*)d_in[10];
    const float* mub  = (const float*)d_in[11];
    const float* msw  = (const float*)d_in[12];
    const float* msb  = (const float*)d_in[13];
    const float* g1w  = (const float*)d_in[14];
    const float* g1b  = (const float*)d_in[15];
    const float* g2w  = (const float*)d_in[16];
    const float* g2b  = (const float*)d_in[17];
    float* out = (float*)d_out;

    cudaFuncSetAttribute(k_msgout, cudaFuncAttributeMaxDynamicSharedMemorySize,
                         MS_SMEM);

    void* zp;
    cudaGetSymbolAddress(&zp, g_zbuf);
    cudaMemsetAsync(zp, 0, ZB_TOTAL * sizeof(float));

    k_pre<<<547 + NEDGES / 256, 256>>>(fcw, c2w, g2w, g2b, ei);

    k_convs<<<BATCH, 256>>>(x, c1w, c1b, c2b);
    k_fc_gemm<<<512, 128>>>();
    k_lgenc<<<512, 256>>>(fcb, muw, mub, act, msw, msb, xmsg, out);

    k_edge1<<<NEDGES / 256, 256>>>(ei, xmsg);
    k_edge2<<<NEDGES / 256, 256>>>(ei, g1w, g1b);

    k_msgout<<<NAGENTS / MS_ROWS, 256, MS_SMEM>>>(g2w, g2b, g1w, g1b, out);
}

// round 17
// speedup vs baseline: 1.3238x; 1.1111x over previous
#include <cuda_runtime.h>
#include <cuda_bf16.h>
#include <cstdint>

// ---------------------------------------------------------------------------
// Sizes (fixed by the problem)
// ---------------------------------------------------------------------------
#define BATCH    256
#define NAGENTS  8192
#define NEDGES   262144
#define ACT      21

#define L2E 1.4426950408889634f
#define LN2 0.6931471805599453f

// ---------------------------------------------------------------------------
// Scratch (device globals: no allocation allowed)
// One contiguous zero-initialized region (single memset):
//   [0, N)              g_deg
//   [N, N+16N)          g_s
//   [N+16N, +BATCH*512) g_hidden (raw GEMM accumulator, bias/relu at read)
// ---------------------------------------------------------------------------
#define ZB_DEG    0
#define ZB_S      (NAGENTS)
#define ZB_HID    (NAGENTS + NAGENTS * 16)
#define ZB_TOTAL  (NAGENTS + NAGENTS * 16 + BATCH * 512)
__device__ __align__(16) float g_zbuf[ZB_TOTAL];
#define g_deg    (g_zbuf + ZB_DEG)
#define g_s      (g_zbuf + ZB_S)
#define g_hidden (g_zbuf + ZB_HID)

__device__ __align__(16) float g_h2t[1024 * BATCH];   // conv2 out, TRANSPOSED [k][m]
__device__ __align__(16) float g_wt[1024 * 512];      // fc_w transposed [k][n]
__device__ __align__(16) float g_w2tp[288 * 65];      // conv2 w, padded transpose [j][oc]
__device__ float  g_enc[NAGENTS];             // actor_encoding[0]
__device__ float  g_dinv[NAGENTS];
__device__ __align__(16) float2 g_AB[NAGENTS];  // rank-2 gcn1 aggregates (final)
__device__ float  g_w2sum[16];
__device__ float  g_b2mean;

// ---------------------------------------------------------------------------
// helpers
// ---------------------------------------------------------------------------
__device__ __forceinline__ unsigned long long fma2(unsigned long long a,
                                                   unsigned long long b,
                                                   unsigned long long c) {
    unsigned long long d;
    asm("fma.rn.f32x2 %0, %1, %2, %3;" : "=l"(d) : "l"(a), "l"(b), "l"(c));
    return d;
}
__device__ __forceinline__ unsigned long long dup2(float v) {
    unsigned u = __float_as_uint(v);
    return ((unsigned long long)u << 32) | (unsigned long long)u;
}
__device__ __forceinline__ unsigned long long pack2(float lo, float hi) {
    return ((unsigned long long)__float_as_uint(hi) << 32) |
           (unsigned long long)__float_as_uint(lo);
}
__device__ __forceinline__ float flo(unsigned long long v) {
    return __uint_as_float((unsigned)v);
}
__device__ __forceinline__ float fhi(unsigned long long v) {
    return __uint_as_float((unsigned)(v >> 32));
}
__device__ __forceinline__ float ex2(float v) {
    float r;
    asm("ex2.approx.ftz.f32 %0, %1;" : "=f"(r) : "f"(v));
    return r;
}
__device__ __forceinline__ void red4(float* p, float a, float b, float c,
                                     float d) {
    asm volatile("red.global.add.v4.f32 [%0], {%1, %2, %3, %4};"
                 :: "l"(p), "f"(a), "f"(b), "f"(c), "f"(d) : "memory");
}
__device__ __forceinline__ void red2(float* p, float a, float b) {
    asm volatile("red.global.add.v2.f32 [%0], {%1, %2};"
                 :: "l"(p), "f"(a), "f"(b) : "memory");
}
__device__ __forceinline__ uint32_t smem_u32(const void* p) {
    uint32_t a;
    asm("{ .reg .u64 t; cvta.to.shared.u64 t, %1; cvt.u32.u64 %0, t; }"
        : "=r"(a) : "l"(p));
    return a;
}

// ---------------------------------------------------------------------------
// k_pre: all independent preprocessing in ONE kernel.
//  blocks [0,512)     : transpose fc_w [512][1024] -> g_wt [1024][512]
//  blocks [512,530)   : pad-transpose c2w [64][288] -> g_w2tp [288][65]
//  blocks [530,547)   : colsum(W2) (16) + mean(b2) (1)
//  blocks [547,1571)  : degree atomics (g_deg pre-zeroed by memset;
//                       self-loop +1 folded into rsqrt at consumption)
// ---------------------------------------------------------------------------
__global__ void __launch_bounds__(256) k_pre(const float* __restrict__ fc_w,
                                             const float* __restrict__ c2w,
                                             const float* __restrict__ W2,
                                             const float* __restrict__ b2,
                                             const int* __restrict__ ei) {
    const int bid = blockIdx.x, tid = threadIdx.x;
    if (bid < 512) {
        __shared__ float t[32][33];
        const int bk = bid & 31;   // 32 k-tiles
        const int bn = bid >> 5;   // 16 n-tiles
        const int tx = tid & 31, ty = tid >> 5;  // 32 x 8
#pragma unroll
        for (int i = 0; i < 32; i += 8)
            t[ty + i][tx] = fc_w[(bn * 32 + ty + i) * 1024 + bk * 32 + tx];
        __syncthreads();
#pragma unroll
        for (int i = 0; i < 32; i += 8)
            g_wt[(bk * 32 + ty + i) * 512 + bn * 32 + tx] = t[tx][ty + i];
    } else if (bid < 530) {
        int base = (bid - 512) * 1024;
#pragma unroll
        for (int q = 0; q < 4; q++) {
            int idx = base + q * 256 + tid;
            if (idx < 64 * 288) {
                int oc = idx / 288, j = idx - oc * 288;
                g_w2tp[j * 65 + oc] = c2w[idx];
            }
        }
    } else if (bid < 547) {
        int k = bid - 530;
        __shared__ float red[256];
        const float* src = (k < 16) ? (W2 + k * NAGENTS) : b2;
        float acc = 0.0f;
        for (int j = tid; j < NAGENTS; j += 256) acc += src[j];
        red[tid] = acc;
        __syncthreads();
        for (int s = 128; s; s >>= 1) {
            if (tid < s) red[tid] += red[tid + s];
            __syncthreads();
        }
        if (tid == 0) {
            if (k < 16) g_w2sum[k] = red[0];
            else        g_b2mean  = red[0] * (1.0f / (float)NAGENTS);
        }
    } else {
        int e = (bid - 547) * 256 + tid;
        if (e < NEDGES) atomicAdd(&g_deg[ei[2 * e + 1]], 1.0f);
    }
}

// ---------------------------------------------------------------------------
// Fused conv1+conv2 per batch element. One CTA per batch.
// ---------------------------------------------------------------------------
__global__ void __launch_bounds__(256) k_convs(const float* __restrict__ x,
                                               const float* __restrict__ c1w,
                                               const float* __restrict__ c1b,
                                               const float* __restrict__ c2b) {
    __shared__ float xs[848];
    __shared__ float h1s[1152];
    __shared__ __align__(16) float w2s[288 * 65];
    const int b = blockIdx.x, tid = threadIdx.x;

    {
        const float4* src = (const float4*)g_w2tp;
        float4* dst = (float4*)w2s;
        for (int i = tid; i < (288 * 65) / 4; i += 256) dst[i] = src[i];
    }
    for (int i = tid; i < 845; i += 256) xs[i] = x[b * 845 + i];
    __syncthreads();

    for (int idx = tid; idx < 1152; idx += 256) {
        int oc = idx / 36, p = idx % 36;
        int oy = p / 6, ox = p % 6;
        const float* wb = c1w + oc * 45;
        float acc = c1b[oc];
#pragma unroll
        for (int ic = 0; ic < 5; ic++)
#pragma unroll
            for (int ky = 0; ky < 3; ky++)
#pragma unroll
                for (int kx = 0; kx < 3; kx++)
                    acc += xs[ic * 169 + (2 * oy + ky) * 13 + 2 * ox + kx] *
                           wb[ic * 9 + ky * 3 + kx];
        h1s[idx] = fmaxf(acc, 0.0f);
    }
    __syncthreads();

    const int oc = tid >> 2, oy = tid & 3;
    float bias = c2b[oc];
    float acc[4];
#pragma unroll
    for (int q = 0; q < 4; q++) acc[q] = bias;

#pragma unroll 4
    for (int ic = 0; ic < 32; ic++) {
#pragma unroll
        for (int ky = 0; ky < 3; ky++) {
            const float* row = &h1s[ic * 36 + (oy + ky) * 6];
            float r0 = row[0], r1 = row[1], r2 = row[2];
            float r3 = row[3], r4 = row[4], r5 = row[5];
            const float* wr = &w2s[(ic * 9 + ky * 3) * 65 + oc];
            float w0 = wr[0], w1 = wr[65], w2 = wr[130];
            acc[0] += r0 * w0 + r1 * w1 + r2 * w2;
            acc[1] += r1 * w0 + r2 * w1 + r3 * w2;
            acc[2] += r2 * w0 + r3 * w1 + r4 * w2;
            acc[3] += r3 * w0 + r4 * w1 + r5 * w2;
        }
    }
    int f0 = oc * 16 + oy * 4;
#pragma unroll
    for (int q = 0; q < 4; q++)
        g_h2t[(f0 + q) * BATCH + b] = fmaxf(acc[q], 0.0f);
}

// ---------------------------------------------------------------------------
// fc GEMM: g_hidden += h2t^T x wt via red.global.add.v4.  512 CTAs, split-K=16.
// ---------------------------------------------------------------------------
__global__ void __launch_bounds__(128) k_fc_gemm() {
    __shared__ float As[64 * 64];   // [k][m]
    __shared__ float Bs[64 * 64];   // [k][n]
    const int bx = blockIdx.x;
    const int ks = bx >> 5;           // 0..15
    const int mt = (bx >> 3) & 3;
    const int nt = bx & 7;
    const int m0 = mt * 64, n0 = nt * 64;
    const int t  = threadIdx.x;
    const int tc = t & 15, tr = t >> 4;
    const int k0 = ks * 64;

    unsigned long long acc[4][4];
#pragma unroll
    for (int p = 0; p < 4; p++)
#pragma unroll
        for (int j = 0; j < 4; j++) acc[p][j] = 0ull;

    const float4* A4g = (const float4*)g_h2t;
    const float4* B4g = (const float4*)g_wt;
    float4* As4w = (float4*)As;
    float4* Bs4w = (float4*)Bs;

#pragma unroll
    for (int j = 0; j < 8; j++) {
        int idx = t + 128 * j;
        int kk = idx >> 4, q = idx & 15;
        As4w[kk * 16 + q] = A4g[((k0 + kk) * BATCH + m0) / 4 + q];
        Bs4w[kk * 16 + q] = B4g[((k0 + kk) * 512 + n0) / 4 + q];
    }
    __syncthreads();

    const float4* As4 = (const float4*)As;
    const float4* Bs4 = (const float4*)Bs;
#pragma unroll 8
    for (int k = 0; k < 64; k++) {
        float4 a0 = As4[k * 16 + tr * 2];
        float4 a1 = As4[k * 16 + tr * 2 + 1];
        float4 bv = Bs4[k * 16 + tc];
        unsigned long long ap[4] = {pack2(a0.x, a0.y), pack2(a0.z, a0.w),
                                    pack2(a1.x, a1.y), pack2(a1.z, a1.w)};
        unsigned long long bd[4] = {dup2(bv.x), dup2(bv.y),
                                    dup2(bv.z), dup2(bv.w)};
#pragma unroll
        for (int p = 0; p < 4; p++)
#pragma unroll
            for (int j = 0; j < 4; j++)
                acc[p][j] = fma2(ap[p], bd[j], acc[p][j]);
    }

#pragma unroll
    for (int p = 0; p < 4; p++) {
        int rlo = m0 + tr * 8 + 2 * p;
        red4(g_hidden + rlo * 512 + n0 + tc * 4,
             flo(acc[p][0]), flo(acc[p][1]), flo(acc[p][2]), flo(acc[p][3]));
        red4(g_hidden + (rlo + 1) * 512 + n0 + tc * 4,
             fhi(acc[p][0]), fhi(acc[p][1]), fhi(acc[p][2]), fhi(acc[p][3]));
    }
}

// ---------------------------------------------------------------------------
// Load one hidden row (raw GEMM accumulator) + bias + relu into smem.
// ---------------------------------------------------------------------------
__device__ __forceinline__ void load_hidden_row(float* hs, int row,
                                                const float* __restrict__ fcb,
                                                int tid) {
    float2 v = ((const float2*)(g_hidden + row * 512))[tid];
    float2 bias = ((const float2*)fcb)[tid];
    ((float2*)hs)[tid] = make_float2(fmaxf(v.x + bias.x, 0.0f),
                                     fmaxf(v.y + bias.y, 0.0f));
}

// ---------------------------------------------------------------------------
// k_lgenc: fused logits head + actor-encoding + gcn node prep.
//  blocks [0,256):   logits/log_prob/entropy/action for batch row bid
//  blocks [256,512): enc for 32 agents/block; msw rows staged into dynamic
//                    SMEM via cp.async.bulk (64KB), dots computed from LDS.
// Output layout: [action(256) | msg_out(8192) | log_prob(256) | entropy(256)]
// ---------------------------------------------------------------------------
#define LG_SMEM 65536

__global__ void __launch_bounds__(256) k_lgenc(const float* __restrict__ fcb,
                                               const float* __restrict__ muw,
                                               const float* __restrict__ mub,
                                               const int* __restrict__ action,
                                               const float* __restrict__ msw,
                                               const float* __restrict__ msb,
                                               const float* __restrict__ xm,
                                               float* __restrict__ out) {
    extern __shared__ __align__(16) float dsm[];   // 64KB staging (enc blocks)
    __shared__ float hs[512];
    __shared__ float lg[24];
    __shared__ __align__(8) unsigned long long mbar;
    const int bid = blockIdx.x, tid = threadIdx.x;
    const int wid = tid >> 5, lane = tid & 31;

    if (bid < 256) {
        load_hidden_row(hs, bid, fcb, tid);
        __syncthreads();

        const float4* h4 = (const float4*)hs;
        for (int a = wid; a < ACT; a += 8) {
            const float4* wr = (const float4*)(muw + a * 512);
            float acc = 0.0f;
#pragma unroll
            for (int i = 0; i < 4; i++) {
                float4 w = wr[lane + i * 32];
                float4 h = h4[lane + i * 32];
                acc += w.x * h.x + w.y * h.y + w.z * h.z + w.w * h.w;
            }
#pragma unroll
            for (int o = 16; o; o >>= 1)
                acc += __shfl_xor_sync(0xffffffffu, acc, o);
            if (lane == 0) lg[a] = acc + mub[a];
        }
        __syncthreads();

        if (wid == 0) {
            float l = (lane < ACT) ? lg[lane] : -3.4e38f;
            float m = l;
#pragma unroll
            for (int o = 16; o; o >>= 1)
                m = fmaxf(m, __shfl_xor_sync(0xffffffffu, m, o));
            float e  = (lane < ACT) ? __expf(l - m) : 0.0f;
            float el = (lane < ACT) ? e * l : 0.0f;
            float se = e, sel = el;
#pragma unroll
            for (int o = 16; o; o >>= 1) {
                se  += __shfl_xor_sync(0xffffffffu, se, o);
                sel += __shfl_xor_sync(0xffffffffu, sel, o);
            }
            int a = action[bid];
            float la = __shfl_sync(0xffffffffu, l, a);
            if (lane == 0) {
                float lse = m + __logf(se);
                out[BATCH + NAGENTS + bid]     = la - lse;        // log_prob
                out[2 * BATCH + NAGENTS + bid] = lse - sel / se;  // entropy
                out[bid] = (float)a;                              // action
            }
        }
    } else {
        const int j0 = (bid - 256) * 32;
        uint32_t mb = smem_u32(&mbar);

        if (tid == 0) {
            asm volatile("mbarrier.init.shared.b64 [%0], 1;"
                         :: "r"(mb) : "memory");
        }
        __syncthreads();
        if (tid == 0) {
            asm volatile(
                "mbarrier.arrive.expect_tx.shared.b64 _, [%0], %1;"
                :: "r"(mb), "r"((uint32_t)LG_SMEM) : "memory");
            asm volatile(
                "cp.async.bulk.shared::cta.global.mbarrier::complete_tx::bytes"
                " [%0], [%1], %2, [%3];"
                :: "r"(smem_u32(dsm)), "l"(msw + (size_t)j0 * 512),
                   "r"((uint32_t)LG_SMEM), "r"(mb) : "memory");
        }
        load_hidden_row(hs, 0, fcb, tid);   // overlaps the bulk copy
        __syncthreads();

        {   // wait for staging
            uint32_t done;
            asm volatile(
                "{\n\t.reg .pred p;\n\t"
                "mbarrier.try_wait.parity.acquire.cta.shared::cta.b64 p, [%1], 0;\n\t"
                "selp.b32 %0, 1, 0, p;\n\t}"
                : "=r"(done) : "r"(mb) : "memory");
            if (!done) {
                asm volatile(
                    "{\n\t.reg .pred P1;\n\t"
                    "W_LOOP:\n\t"
                    "mbarrier.try_wait.parity.acquire.cta.shared::cta.b64 P1, [%0], 0, 0x989680;\n\t"
                    "@P1 bra.uni W_DONE;\n\t"
                    "bra.uni W_LOOP;\n\t"
                    "W_DONE:\n\t}"
                    :: "r"(mb) : "memory");
            }
        }

        // 4 rows per warp, dots from SMEM (conflict-free)
        const int r0 = wid * 4;
        const float4* h4 = (const float4*)hs;
        const float4* w4 = (const float4*)dsm;
        float acc[4] = {0.0f, 0.0f, 0.0f, 0.0f};
#pragma unroll
        for (int i = 0; i < 4; i++) {
            float4 h = h4[lane + i * 32];
#pragma unroll
            for (int q = 0; q < 4; q++) {
                float4 w = w4[(r0 + q) * 128 + lane + i * 32];
                acc[q] += w.x * h.x + w.y * h.y + w.z * h.z + w.w * h.w;
            }
        }
#pragma unroll
        for (int o = 16; o; o >>= 1)
#pragma unroll
            for (int q = 0; q < 4; q++)
                acc[q] += __shfl_xor_sync(0xffffffffu, acc[q], o);
        if (lane == 0) {
#pragma unroll
            for (int q = 0; q < 4; q++) {
                int j = j0 + r0 + q;
                float e = acc[q] + msb[j];
                g_enc[j] = e;
                float dv = rsqrtf(g_deg[j] + 1.0f);   // +1 = self loop
                g_dinv[j] = dv;
                float d2 = dv * dv;                   // self-loop norm
                g_AB[j] = make_float2(d2 * xm[j], d2 * e);
            }
        }
    }
}

// ---------------------------------------------------------------------------
// GCN edge aggregation. g1 recomputed on the fly from AB (rank-2).
// ---------------------------------------------------------------------------
__global__ void k_edge1(const int* __restrict__ ei,
                        const float* __restrict__ xm) {
    int e = blockIdx.x * 256 + threadIdx.x;
    if (e >= NEDGES) return;
    int s = ei[2 * e], d = ei[2 * e + 1];
    float nrm = g_dinv[s] * g_dinv[d];
    red2((float*)&g_AB[d], nrm * xm[s], nrm * g_enc[s]);
}

__global__ void __launch_bounds__(256) k_edge2(const int* __restrict__ ei,
                                               const float* __restrict__ w1,
                                               const float* __restrict__ b1) {
    __shared__ float w1s[48];
    const int tid = threadIdx.x;
    if (tid < 48) w1s[tid] = (tid < 32) ? w1[tid] : b1[tid - 32];
    __syncthreads();

    int e = blockIdx.x * 256 + tid;
    if (e >= NEDGES) return;
    int s = ei[2 * e], d = ei[2 * e + 1];
    float nrm = g_dinv[s] * g_dinv[d];
    float2 ab = g_AB[s];
    float* sd = g_s + d * 16;
#pragma unroll
    for (int q = 0; q < 4; q++) {
        float v0 = fmaxf(ab.x * w1s[q*4+0] + ab.y * w1s[16+q*4+0] + w1s[32+q*4+0], 0.0f);
        float v1 = fmaxf(ab.x * w1s[q*4+1] + ab.y * w1s[16+q*4+1] + w1s[32+q*4+1], 0.0f);
        float v2 = fmaxf(ab.x * w1s[q*4+2] + ab.y * w1s[16+q*4+2] + w1s[32+q*4+2], 0.0f);
        float v3 = fmaxf(ab.x * w1s[q*4+3] + ab.y * w1s[16+q*4+3] + w1s[32+q*4+3], 0.0f);
        red4(sd + q * 4, nrm * v0, nrm * v1, nrm * v2, nrm * v3);
    }
}

// ---------------------------------------------------------------------------
// K12: msg_out[i] = mean_j(g_ij) - lse_j(g_ij), g_ij = s[i].W2[:,j]+b2[j].
// 32 rows/CTA (halves W2 re-streaming vs 16), W2 in 16x1024 SMEM chunks,
// f32x2 FMA, log2-domain + raw ex2, k-pairs with ulonglong2 sdup loads.
// ---------------------------------------------------------------------------
#define MS_CHUNK 1024
#define MS_ROWS  32
#define MS_SMEM  (16 * MS_CHUNK * 4 + MS_ROWS * 16 * 8 + MS_ROWS * 16 * 4)

__global__ void __launch_bounds__(256) k_msgout(const float* __restrict__ W2,
                                                const float* __restrict__ b2,
                                                const float* __restrict__ w1,
                                                const float* __restrict__ b1,
                                                float* __restrict__ out) {
    extern __shared__ char smraw[];
    float* wsm = (float*)smraw;                                    // 16*1024 f
    unsigned long long* sdup =
        (unsigned long long*)(smraw + 16 * MS_CHUNK * 4);          // 512 u64
    float* slin = (float*)(smraw + 16 * MS_CHUNK * 4 + 512 * 8);   // 512 f

    const int tid  = threadIdx.x;
    const int row0 = blockIdx.x * MS_ROWS;

#pragma unroll
    for (int it = 0; it < 2; it++) {
        int idx = tid + it * 256;
        int r = idx >> 4, k = idx & 15;
        int row = row0 + r;
        float dv = g_dinv[row];
        float2 ab = g_AB[row];
        float v = fmaxf(ab.x * w1[k] + ab.y * w1[16 + k] + b1[k], 0.0f);
        float sfin = g_s[row * 16 + k] + dv * dv * v;
        slin[idx] = sfin;
        sdup[idx] = dup2(sfin * L2E);
    }

    float sr[MS_ROWS];
#pragma unroll
    for (int r = 0; r < MS_ROWS; r++) sr[r] = 0.0f;

    const float4* gw4 = (const float4*)W2;

    for (int chunk = 0; chunk < NAGENTS / MS_CHUNK; chunk++) {
        int base = chunk * MS_CHUNK;
        __syncthreads();
#pragma unroll
        for (int k = 0; k < 16; k++)
            ((float4*)wsm)[k * 256 + tid] = gw4[(k * NAGENTS + base) / 4 + tid];
        float4 bb = ((const float4*)(b2 + base))[tid];
        __syncthreads();

        unsigned long long acc0[MS_ROWS], acc1[MS_ROWS];
        unsigned long long b01 = pack2(bb.x * L2E, bb.y * L2E);
        unsigned long long b23 = pack2(bb.z * L2E, bb.w * L2E);
#pragma unroll
        for (int r = 0; r < MS_ROWS; r++) { acc0[r] = b01; acc1[r] = b23; }

        const ulonglong2* wU2 = (const ulonglong2*)wsm;
        const ulonglong2* sd2 = (const ulonglong2*)sdup;  // pairs (k, k+1)
#pragma unroll
        for (int kp = 0; kp < 8; kp++) {
            ulonglong2 wa = wU2[(2 * kp) * 256 + tid];
            ulonglong2 wb = wU2[(2 * kp + 1) * 256 + tid];
#pragma unroll
            for (int r = 0; r < MS_ROWS; r++) {
                ulonglong2 sv = sd2[r * 8 + kp];   // broadcast LDS.128
                acc0[r] = fma2(wa.x, sv.x, acc0[r]);
                acc1[r] = fma2(wa.y, sv.x, acc1[r]);
                acc0[r] = fma2(wb.x, sv.y, acc0[r]);
                acc1[r] = fma2(wb.y, sv.y, acc1[r]);
            }
        }
#pragma unroll
        for (int r = 0; r < MS_ROWS; r++) {
            sr[r] += ex2(flo(acc0[r])) + ex2(fhi(acc0[r])) +
                     ex2(flo(acc1[r])) + ex2(fhi(acc1[r]));
        }
    }

    // block sum-reduce per row; alias onto wsm (32KB)
    __syncthreads();
    float* rs = wsm;              // [32][256]
#pragma unroll
    for (int r = 0; r < MS_ROWS; r++) rs[r * 256 + tid] = sr[r];
    for (int step = 128; step > 0; step >>= 1) {
        __syncthreads();
        if (tid < step) {
#pragma unroll
            for (int r = 0; r < MS_ROWS; r++)
                rs[r * 256 + tid] += rs[r * 256 + tid + step];
        }
    }
    __syncthreads();
    if (tid < MS_ROWS) {
        int row = row0 + tid;
        float lse = LN2 * __log2f(rs[tid * 256]);
        float acc = 0.0f;
#pragma unroll
        for (int k = 0; k < 16; k++) acc += slin[tid * 16 + k] * g_w2sum[k];
        out[BATCH + row] = acc * (1.0f / (float)NAGENTS) + g_b2mean - lse;
    }
}

// ---------------------------------------------------------------------------
// launch (7 kernels + 1 memset)
// ---------------------------------------------------------------------------
extern "C" void kernel_launch(void* const* d_in, const int* in_sizes, int n_in,
                              void* d_out, int out_size) {
    const float* x    = (const float*)d_in[0];
    const float* xmsg = (const float*)d_in[1];
    const int*   ei   = (const int*)d_in[2];
    const int*   act  = (const int*)d_in[3];
    const float* c1w  = (const float*)d_in[4];
    const float* c1b  = (const float*)d_in[5];
    const float* c2w  = (const float*)d_in[6];
    const float* c2b  = (const float*)d_in[7];
    const float* fcw  = (const float*)d_in[8];
    const float* fcb  = (const float*)d_in[9];
    const float* muw  = (const float*)d_in[10];
    const float* mub  = (const float*)d_in[11];
    const float* msw  = (const float*)d_in[12];
    const float* msb  = (const float*)d_in[13];
    const float* g1w  = (const float*)d_in[14];
    const float* g1b  = (const float*)d_in[15];
    const float* g2w  = (const float*)d_in[16];
    const float* g2b  = (const float*)d_in[17];
    float* out = (float*)d_out;

    cudaFuncSetAttribute(k_msgout, cudaFuncAttributeMaxDynamicSharedMemorySize,
                         MS_SMEM);
    cudaFuncSetAttribute(k_lgenc, cudaFuncAttributeMaxDynamicSharedMemorySize,
                         LG_SMEM);

    void* zp;
    cudaGetSymbolAddress(&zp, g_zbuf);
    cudaMemsetAsync(zp, 0, ZB_TOTAL * sizeof(float));

    k_pre<<<547 + NEDGES / 256, 256>>>(fcw, c2w, g2w, g2b, ei);

    k_convs<<<BATCH, 256>>>(x, c1w, c1b, c2b);
    k_fc_gemm<<<512, 128>>>();
    k_lgenc<<<512, 256, LG_SMEM>>>(fcb, muw, mub, act, msw, msb, xmsg, out);

    k_edge1<<<NEDGES / 256, 256>>>(ei, xmsg);
    k_edge2<<<NEDGES / 256, 256>>>(ei, g1w, g1b);

    k_msgout<<<NAGENTS / MS_ROWS, 256, MS_SMEM>>>(g2w, g2b, g1w, g1b, out);
}